// round 9
// baseline (speedup 1.0000x reference)
#include <cuda_runtime.h>
#include <cuda_bf16.h>
#include <cuda_fp8.h>
#include <cstdint>
#include <cstddef>

#define BATCH 4
#define CCH 256
#define NTOK 4096
#define GROUPS 32
#define CPG 8
#define EPSV 1e-6f

typedef __nv_bfloat16 bf16;

// ---------------- scratch ----------------
__device__ uint4 g_xnb4 [(size_t)BATCH * CCH * NTOK / 8];        // bf16 GN out
__device__ uint4 g_qkv8 [(size_t)3 * BATCH * CCH * NTOK / 16];   // fp8 q,k,v (12MB)
__device__ uint4 g_ob4  [(size_t)BATCH * CCH * NTOK / 8];        // bf16 PV out
__device__ uint4 g_attn8[(size_t)BATCH * NTOK * NTOK / 16];      // fp8 P (64MB)
__device__ uint4 g_wb4[4][CCH * CCH / 8];
__device__ float g_biasqkv[3 * CCH];
__device__ float g_psum[(size_t)BATCH * NTOK * 32];
__device__ float g_invs[BATCH * NTOK];
__device__ float g_gnstat[BATCH * GROUPS * 4 * 2];

// ---------------- asm helpers ----------------
__device__ __forceinline__ uint32_t smem_u32(const void* p) {
    uint32_t a;
    asm("{ .reg .u64 t; cvta.to.shared.u64 t, %1; cvt.u32.u64 %0, t; }"
        : "=r"(a) : "l"(p));
    return a;
}
__device__ __forceinline__ void ldsm4(uint32_t* r, uint32_t a) {
    asm volatile("ldmatrix.sync.aligned.m8n8.x4.shared.b16 {%0,%1,%2,%3}, [%4];"
        : "=r"(r[0]), "=r"(r[1]), "=r"(r[2]), "=r"(r[3]) : "r"(a));
}
__device__ __forceinline__ void ldsm4t(uint32_t* r, uint32_t a) {
    asm volatile("ldmatrix.sync.aligned.m8n8.x4.trans.shared.b16 {%0,%1,%2,%3}, [%4];"
        : "=r"(r[0]), "=r"(r[1]), "=r"(r[2]), "=r"(r[3]) : "r"(a));
}
__device__ __forceinline__ void mma16(float* c, const uint32_t* a,
                                      uint32_t b0, uint32_t b1) {
    asm volatile(
        "mma.sync.aligned.m16n8k16.row.col.f32.bf16.bf16.f32 "
        "{%0,%1,%2,%3}, {%4,%5,%6,%7}, {%8,%9}, {%0,%1,%2,%3};"
        : "+f"(c[0]), "+f"(c[1]), "+f"(c[2]), "+f"(c[3])
        : "r"(a[0]), "r"(a[1]), "r"(a[2]), "r"(a[3]), "r"(b0), "r"(b1));
}
__device__ __forceinline__ void mma32(float* c, const uint32_t* a,
                                      uint32_t b0, uint32_t b1) {
    asm volatile(
        "mma.sync.aligned.m16n8k32.row.col.f32.e4m3.e4m3.f32 "
        "{%0,%1,%2,%3}, {%4,%5,%6,%7}, {%8,%9}, {%0,%1,%2,%3};"
        : "+f"(c[0]), "+f"(c[1]), "+f"(c[2]), "+f"(c[3])
        : "r"(a[0]), "r"(a[1]), "r"(a[2]), "r"(a[3]), "r"(b0), "r"(b1));
}
__device__ __forceinline__ void cp16(uint32_t d, const void* s) {
    asm volatile("cp.async.cg.shared.global [%0], [%1], 16;" :: "r"(d), "l"(s));
}
// pack two floats into e4m3x2 (lo -> low byte, hi -> high byte)
__device__ __forceinline__ uint16_t fp8x2(float lo, float hi) {
    uint16_t r;
    asm("cvt.rn.satfinite.e4m3x2.f32 %0, %1, %2;" : "=h"(r) : "f"(hi), "f"(lo));
    return r;
}

// ---------------------------------------------------------------------------
__global__ void convw_kernel(const float* wq, const float* wk,
                             const float* wv, const float* wo,
                             const float* bq, const float* bk, const float* bv,
                             bf16* w0, bf16* w1, bf16* w2, bf16* w3,
                             float* biasqkv) {
    int i = blockIdx.x * 256 + threadIdx.x;
    w0[i] = __float2bfloat16(wq[i]);
    w1[i] = __float2bfloat16(wk[i]);
    w2[i] = __float2bfloat16(wv[i]);
    w3[i] = __float2bfloat16(wo[i]);
    if (i < CCH) {
        biasqkv[i]           = bq[i];
        biasqkv[CCH + i]     = bk[i];
        biasqkv[2 * CCH + i] = bv[i];
    }
}

// ---------------------------------------------------------------------------
__global__ void gn_stats_kernel(const float* __restrict__ x,
                                float* __restrict__ stat) {
    const float4* xp = (const float4*)(x + (size_t)blockIdx.x * 8192);
    int tid = threadIdx.x;
    float s = 0.f, s2 = 0.f;
    #pragma unroll
    for (int i = 0; i < 8; i++) {
        float4 v = xp[tid + i * 256];
        s  += v.x + v.y + v.z + v.w;
        s2 += v.x*v.x + v.y*v.y + v.z*v.z + v.w*v.w;
    }
    __shared__ float sh0[256], sh1[256];
    sh0[tid] = s; sh1[tid] = s2;
    __syncthreads();
    for (int off = 128; off > 0; off >>= 1) {
        if (tid < off) { sh0[tid] += sh0[tid + off]; sh1[tid] += sh1[tid + off]; }
        __syncthreads();
    }
    if (tid == 0) {
        stat[blockIdx.x * 2]     = sh0[0];
        stat[blockIdx.x * 2 + 1] = sh1[0];
    }
}

__global__ void gn_apply_kernel(const float* __restrict__ x,
                                const float* __restrict__ stat,
                                const float* __restrict__ w,
                                const float* __restrict__ b,
                                bf16* __restrict__ xnb) {
    int blk = blockIdx.x;
    int bg  = blk >> 2;
    int grp = bg % GROUPS;
    float s  = stat[bg * 8 + 0] + stat[bg * 8 + 2] +
               stat[bg * 8 + 4] + stat[bg * 8 + 6];
    float s2 = stat[bg * 8 + 1] + stat[bg * 8 + 3] +
               stat[bg * 8 + 5] + stat[bg * 8 + 7];
    const float nall = (float)(CPG * NTOK);
    float mean = s / nall;
    float var  = s2 / nall - mean * mean;
    float rstd = rsqrtf(var + EPSV);

    size_t base = (size_t)blk * 8192;
    const float4* xp = (const float4*)(x + base);
    bf16* op = xnb + base;
    int tid = threadIdx.x;
    #pragma unroll
    for (int i = 0; i < 8; i++) {
        int idx = tid + i * 256;
        int ch = grp * CPG + (int)(((blk & 3) * 8192 + idx * 4) / NTOK);
        float sc = rstd * w[ch];
        float sb = b[ch] - mean * sc;
        float4 v = xp[idx];
        __nv_bfloat162 h0 = __floats2bfloat162_rn(v.x * sc + sb, v.y * sc + sb);
        __nv_bfloat162 h1 = __floats2bfloat162_rn(v.z * sc + sb, v.w * sc + sb);
        uint2 u;
        u.x = *(uint32_t*)&h0; u.y = *(uint32_t*)&h1;
        *(uint2*)(op + idx * 4) = u;
    }
}

// ---------------------------------------------------------------------------
__global__ void rowinv_kernel(const float* __restrict__ psum,
                              float* __restrict__ invs) {
    int i = blockIdx.x * 256 + threadIdx.x;
    const float4* p = (const float4*)(psum + (size_t)i * 32);
    float s = 0.f;
    #pragma unroll
    for (int j = 0; j < 8; j++) {
        float4 a = p[j];
        s += a.x + a.y + a.z + a.w;
    }
    invs[i] = 1.f / s;
}

// ---------------------------------------------------------------------------
// bf16 GEMM (QKV + output projection). CTA 128x128, BK=64, 4 warps @ 64x64.
// OUTF 1: fp32 out + bias + resid.
// OUTF 4: QKV fp8 outputs: mat 0/1 (q,k) -> transposed [tok][ch] bytes,
//         mat 2 (v) -> native [ch][tok] e4m3x2 pairs.
// ---------------------------------------------------------------------------
#define ABYTES 18432u
#define STAGEB 36864u
#define SMEM_B16 (3 * 36864)

template <int OUTF, int QKV>
__global__ void __launch_bounds__(128, 2)
bgemm(const bf16* __restrict__ A, const bf16* __restrict__ B,
      const float* __restrict__ bias, const float* __restrict__ resid,
      void* __restrict__ Cv,
      int K, int lda, int ldb, int ldc,
      size_t sA, size_t sB, size_t sC, size_t sR) {
    extern __shared__ __align__(16) char smem[];
    const int bz = blockIdx.z;

    int M0, mat = 0;
    if (QKV) {
        mat = blockIdx.y >> 1;
        A    += (size_t)mat * (CCH * CCH);
        bias += mat * CCH;
        M0 = (blockIdx.y & 1) * 128;
    } else {
        M0 = blockIdx.y * 128;
    }
    A += (size_t)bz * sA;
    B += (size_t)bz * sB;

    const int N0 = blockIdx.x * 128;
    const int tid  = threadIdx.x;
    const int lane = tid & 31;
    const int wid  = tid >> 5;
    const int wm = wid >> 1;
    const int wn = wid & 1;
    const int g  = lane >> 2;
    const int t  = lane & 3;
    const int l7  = lane & 7;
    const int l15 = lane & 15;
    const int b3 = (lane >> 3) & 1;
    const int b4 = (lane >> 4) & 1;

    const uint32_t smem_u = smem_u32(smem);

    float acc[4][8][4];
    #pragma unroll
    for (int i = 0; i < 4; i++)
        #pragma unroll
        for (int j = 0; j < 8; j++)
            #pragma unroll
            for (int q = 0; q < 4; q++) acc[i][j][q] = 0.f;

    const int KT = K >> 6;

    auto stage = [&](int kt, int buf) {
        uint32_t ab = smem_u + (uint32_t)buf * STAGEB;
        uint32_t bbs = ab + ABYTES;
        int k0 = kt << 6;
        #pragma unroll
        for (int i = 0; i < 8; i++) {           // A [m][k] k-cont
            int c = tid + i * 128;
            int m = c >> 3, kc = c & 7;
            cp16(ab + (uint32_t)(m * 72 + kc * 8) * 2,
                 A + (size_t)(M0 + m) * lda + k0 + kc * 8);
        }
        #pragma unroll
        for (int i = 0; i < 8; i++) {           // B [k][n] n-cont
            int c = tid + i * 128;
            int k = c >> 4, nc = c & 15;
            cp16(bbs + (uint32_t)(k * 136 + nc * 8) * 2,
                 B + (size_t)(k0 + k) * ldb + N0 + nc * 8);
        }
    };

    stage(0, 0);
    asm volatile("cp.async.commit_group;" ::: "memory");
    stage(1, 1);
    asm volatile("cp.async.commit_group;" ::: "memory");

    for (int kt = 0; kt < KT; kt++) {
        asm volatile("cp.async.wait_group 1;" ::: "memory");
        __syncthreads();
        if (kt + 2 < KT) stage(kt + 2, (kt + 2) % 3);
        asm volatile("cp.async.commit_group;" ::: "memory");

        uint32_t ab = smem_u + (uint32_t)(kt % 3) * STAGEB;
        uint32_t bbs = ab + ABYTES;

        #pragma unroll
        for (int ks = 0; ks < 4; ks++) {
            uint32_t af[4][4];
            #pragma unroll
            for (int i = 0; i < 4; i++) {
                uint32_t addr = ab + 2u * (uint32_t)(
                    (wm * 64 + i * 16 + l15) * 72 + ks * 16 + b4 * 8);
                ldsm4(af[i], addr);
            }
            uint32_t bfr[4][4];
            #pragma unroll
            for (int j2 = 0; j2 < 4; j2++) {
                int nb = wn * 64 + j2 * 16;
                uint32_t addr = bbs + 2u * (uint32_t)(
                    (ks * 16 + b3 * 8 + l7) * 136 + nb + b4 * 8);
                ldsm4t(bfr[j2], addr);
            }
            #pragma unroll
            for (int j2 = 0; j2 < 4; j2++) {
                #pragma unroll
                for (int i = 0; i < 4; i++) {
                    mma16(acc[i][2*j2],     af[i], bfr[j2][0], bfr[j2][1]);
                    mma16(acc[i][2*j2 + 1], af[i], bfr[j2][2], bfr[j2][3]);
                }
            }
        }
    }

    if (OUTF == 1) {
        float* C = (float*)Cv + (size_t)bz * sC;
        const float* R = resid + (size_t)bz * sR;
        #pragma unroll
        for (int i = 0; i < 4; i++) {
            int m = M0 + wm * 64 + i * 16 + g;
            float bm0 = bias[m];
            float bm1 = bias[m + 8];
            #pragma unroll
            for (int j = 0; j < 8; j++) {
                int n = N0 + wn * 64 + j * 8 + 2 * t;
                float2 r0 = *(const float2*)(R + (size_t)m * ldc + n);
                float2 r1 = *(const float2*)(R + (size_t)(m + 8) * ldc + n);
                float2 v0, v1;
                v0.x = acc[i][j][0] + bm0 + r0.x;
                v0.y = acc[i][j][1] + bm0 + r0.y;
                v1.x = acc[i][j][2] + bm1 + r1.x;
                v1.y = acc[i][j][3] + bm1 + r1.y;
                *(float2*)(C + (size_t)m * ldc + n)       = v0;
                *(float2*)(C + (size_t)(m + 8) * ldc + n) = v1;
            }
        }
    } else {
        // OUTF == 4: fp8 QKV outputs
        uint8_t* Q8 = (uint8_t*)Cv;
        uint8_t* K8 = Q8 + (size_t)BATCH * NTOK * CCH;
        uint8_t* V8 = K8 + (size_t)BATCH * NTOK * CCH;
        if (mat == 2) {
            uint8_t* V = V8 + (size_t)bz * CCH * NTOK;   // [c][tok]
            #pragma unroll
            for (int i = 0; i < 4; i++) {
                int m = M0 + wm * 64 + i * 16 + g;
                float bm0 = bias[m];
                float bm1 = bias[m + 8];
                #pragma unroll
                for (int j = 0; j < 8; j++) {
                    int n = N0 + wn * 64 + j * 8 + 2 * t;
                    *(uint16_t*)(V + (size_t)m * NTOK + n) =
                        fp8x2(acc[i][j][0] + bm0, acc[i][j][1] + bm0);
                    *(uint16_t*)(V + (size_t)(m + 8) * NTOK + n) =
                        fp8x2(acc[i][j][2] + bm1, acc[i][j][3] + bm1);
                }
            }
        } else {
            uint8_t* T = (mat ? K8 : Q8) + (size_t)bz * NTOK * CCH;  // [tok][c]
            #pragma unroll
            for (int i = 0; i < 4; i++) {
                int m = M0 + wm * 64 + i * 16 + g;
                float bm0 = bias[m];
                float bm1 = bias[m + 8];
                #pragma unroll
                for (int j = 0; j < 8; j++) {
                    int n = N0 + wn * 64 + j * 8 + 2 * t;
                    T[(size_t)n * CCH + m]           = (uint8_t)__nv_fp8_e4m3(acc[i][j][0] + bm0).__x;
                    T[(size_t)(n + 1) * CCH + m]     = (uint8_t)__nv_fp8_e4m3(acc[i][j][1] + bm0).__x;
                    T[(size_t)n * CCH + m + 8]       = (uint8_t)__nv_fp8_e4m3(acc[i][j][2] + bm1).__x;
                    T[(size_t)(n + 1) * CCH + m + 8] = (uint8_t)__nv_fp8_e4m3(acc[i][j][3] + bm1).__x;
                }
            }
        }
    }
}

// ---------------------------------------------------------------------------
// fp8 GEMM (scores + PV). CTA 128x128, BK=64 bytes, 4 warps @ 64x64.
// A [m][k] k-cont fp8, B [n][k] k-cont fp8, smem row stride 80 bytes.
// OUTF 2: P = exp(acc*alpha) fp8 out + partial row sums.
// OUTF 3: bf16 out scaled by invs[n].
// ---------------------------------------------------------------------------
#define F_AB 10240u
#define F_STAGE 20480u
#define SMEM_F8 (3 * 20480)

template <int OUTF>
__global__ void __launch_bounds__(128, 2)
fgemm(const uint8_t* __restrict__ A, const uint8_t* __restrict__ B,
      void* __restrict__ Cv, float* __restrict__ psum,
      const float* __restrict__ invs,
      int K, int lda, int ldb, int ldc,
      size_t sA, size_t sB, size_t sC, float alpha) {
    extern __shared__ __align__(16) char smem[];
    const int bz = blockIdx.z;
    A += (size_t)bz * sA;
    B += (size_t)bz * sB;

    const int M0 = blockIdx.y * 128;
    const int N0 = blockIdx.x * 128;
    const int tid  = threadIdx.x;
    const int lane = tid & 31;
    const int wid  = tid >> 5;
    const int wm = wid >> 1;
    const int wn = wid & 1;
    const int g  = lane >> 2;
    const int t  = lane & 3;
    const int l7  = lane & 7;
    const int l15 = lane & 15;
    const int b3 = (lane >> 3) & 1;
    const int b4 = (lane >> 4) & 1;

    const uint32_t smem_u = smem_u32(smem);

    float acc[4][8][4];
    #pragma unroll
    for (int i = 0; i < 4; i++)
        #pragma unroll
        for (int j = 0; j < 8; j++)
            #pragma unroll
            for (int q = 0; q < 4; q++) acc[i][j][q] = 0.f;

    const int KT = K >> 6;    // 64-byte k-tiles

    auto stage = [&](int kt, int buf) {
        uint32_t ab = smem_u + (uint32_t)buf * F_STAGE;
        uint32_t bbs = ab + F_AB;
        int k0 = kt << 6;
        #pragma unroll
        for (int i = 0; i < 4; i++) {           // A: 128 rows x 64B
            int c = tid + i * 128;
            int m = c >> 2, kc = c & 3;
            cp16(ab + (uint32_t)(m * 80 + kc * 16),
                 A + (size_t)(M0 + m) * lda + k0 + kc * 16);
        }
        #pragma unroll
        for (int i = 0; i < 4; i++) {           // B: 128 rows x 64B
            int c = tid + i * 128;
            int n = c >> 2, kc = c & 3;
            cp16(bbs + (uint32_t)(n * 80 + kc * 16),
                 B + (size_t)(N0 + n) * ldb + k0 + kc * 16);
        }
    };

    stage(0, 0);
    asm volatile("cp.async.commit_group;" ::: "memory");
    stage(1, 1);
    asm volatile("cp.async.commit_group;" ::: "memory");

    for (int kt = 0; kt < KT; kt++) {
        asm volatile("cp.async.wait_group 1;" ::: "memory");
        __syncthreads();
        if (kt + 2 < KT) stage(kt + 2, (kt + 2) % 3);
        asm volatile("cp.async.commit_group;" ::: "memory");

        uint32_t ab = smem_u + (uint32_t)(kt % 3) * F_STAGE;
        uint32_t bbs = ab + F_AB;

        #pragma unroll
        for (int ks = 0; ks < 2; ks++) {        // two k32 steps per 64B tile
            uint32_t af[4][4];
            #pragma unroll
            for (int i = 0; i < 4; i++) {
                // lanes 0-15 -> rows (bytes 0-15), lanes 16-31 -> bytes 16-31
                uint32_t addr = ab +
                    (uint32_t)((wm * 64 + i * 16 + l15) * 80 + ks * 32 + b4 * 16);
                ldsm4(af[i], addr);   // r0..r3 = a0..a3
            }
            uint32_t bfr[4][4];
            #pragma unroll
            for (int j2 = 0; j2 < 4; j2++) {
                int nb = wn * 64 + j2 * 16;
                uint32_t addr = bbs +
                    (uint32_t)((nb + b3 * 8 + l7) * 80 + ks * 32 + b4 * 16);
                ldsm4(bfr[j2], addr); // r0=b0 nLo, r1=b0 nHi, r2=b1 nLo, r3=b1 nHi
            }
            #pragma unroll
            for (int j2 = 0; j2 < 4; j2++) {
                #pragma unroll
                for (int i = 0; i < 4; i++) {
                    mma32(acc[i][2*j2],     af[i], bfr[j2][0], bfr[j2][2]);
                    mma32(acc[i][2*j2 + 1], af[i], bfr[j2][1], bfr[j2][3]);
                }
            }
        }
    }

    if (OUTF == 2) {
        // exp epilogue -> fp8 P + partial row sums
        uint8_t* P = (uint8_t*)Cv + (size_t)bz * sC;
        float* ps = (float*)smem;          // [2][128]
        __syncthreads();
        #pragma unroll
        for (int i = 0; i < 4; i++) {
            int m = M0 + wm * 64 + i * 16 + g;
            float sr0 = 0.f, sr1 = 0.f;
            #pragma unroll
            for (int j = 0; j < 8; j++) {
                int n = N0 + wn * 64 + j * 8 + 2 * t;
                float e0 = __expf(acc[i][j][0] * alpha);
                float e1 = __expf(acc[i][j][1] * alpha);
                float e2 = __expf(acc[i][j][2] * alpha);
                float e3 = __expf(acc[i][j][3] * alpha);
                sr0 += e0 + e1;
                sr1 += e2 + e3;
                *(uint16_t*)(P + (size_t)m * ldc + n)       = fp8x2(e0, e1);
                *(uint16_t*)(P + (size_t)(m + 8) * ldc + n) = fp8x2(e2, e3);
            }
            sr0 += __shfl_xor_sync(0xffffffffu, sr0, 1);
            sr0 += __shfl_xor_sync(0xffffffffu, sr0, 2);
            sr1 += __shfl_xor_sync(0xffffffffu, sr1, 1);
            sr1 += __shfl_xor_sync(0xffffffffu, sr1, 2);
            if (t == 0) {
                int r = wm * 64 + i * 16 + g;
                ps[wn * 128 + r]     = sr0;
                ps[wn * 128 + r + 8] = sr1;
            }
        }
        __syncthreads();
        float tot = ps[tid] + ps[128 + tid];
        psum[((size_t)bz * NTOK + M0 + tid) * 32 + blockIdx.x] = tot;
    } else {
        // OUTF == 3: normalize by invs[n], bf16 out
        bf16* C = (bf16*)Cv + (size_t)bz * sC;
        const float* iv = invs + (size_t)bz * NTOK;
        #pragma unroll
        for (int i = 0; i < 4; i++) {
            int m = M0 + wm * 64 + i * 16 + g;
            #pragma unroll
            for (int j = 0; j < 8; j++) {
                int n = N0 + wn * 64 + j * 8 + 2 * t;
                float2 w2 = *(const float2*)(iv + n);
                *(__nv_bfloat162*)(C + (size_t)m * ldc + n) =
                    __floats2bfloat162_rn(acc[i][j][0] * w2.x, acc[i][j][1] * w2.y);
                *(__nv_bfloat162*)(C + (size_t)(m + 8) * ldc + n) =
                    __floats2bfloat162_rn(acc[i][j][2] * w2.x, acc[i][j][3] * w2.y);
            }
        }
    }
}

// ---------------------------------------------------------------------------
extern "C" void kernel_launch(void* const* d_in, const int* in_sizes, int n_in,
                              void* d_out, int out_size) {
    const float* x    = (const float*)d_in[0];
    const float* gn_w = (const float*)d_in[1];
    const float* gn_b = (const float*)d_in[2];
    const float* wq   = (const float*)d_in[3];
    const float* bq   = (const float*)d_in[4];
    const float* wk   = (const float*)d_in[5];
    const float* bk   = (const float*)d_in[6];
    const float* wv   = (const float*)d_in[7];
    const float* bv   = (const float*)d_in[8];
    const float* wo   = (const float*)d_in[9];
    const float* bo   = (const float*)d_in[10];
    float* out = (float*)d_out;

    void *p_xn, *p_qkv, *p_o, *p_attn, *p_w, *p_bias, *p_psum, *p_inv, *p_stat;
    cudaGetSymbolAddress(&p_xn,   g_xnb4);
    cudaGetSymbolAddress(&p_qkv,  g_qkv8);
    cudaGetSymbolAddress(&p_o,    g_ob4);
    cudaGetSymbolAddress(&p_attn, g_attn8);
    cudaGetSymbolAddress(&p_w,    g_wb4);
    cudaGetSymbolAddress(&p_bias, g_biasqkv);
    cudaGetSymbolAddress(&p_psum, g_psum);
    cudaGetSymbolAddress(&p_inv,  g_invs);
    cudaGetSymbolAddress(&p_stat, g_gnstat);

    bf16* xnb  = (bf16*)p_xn;
    uint8_t* qkv8 = (uint8_t*)p_qkv;
    uint8_t* atb8 = (uint8_t*)p_attn;
    bf16* ob   = (bf16*)p_o;
    bf16* wqb  = (bf16*)p_w;
    bf16* wob  = wqb + 3 * CCH * CCH;
    float* biasqkv = (float*)p_bias;
    float* psum = (float*)p_psum;
    float* invs = (float*)p_inv;
    float* stat = (float*)p_stat;

    const size_t SBb = (size_t)CCH * NTOK;   // elements per batch feature map
    const size_t SAb = (size_t)NTOK * NTOK;  // bytes per batch attn (fp8)
    uint8_t* q8 = qkv8;                              // [b][tok][c]
    uint8_t* k8 = qkv8 + (size_t)BATCH * SBb;        // [b][tok][c]
    uint8_t* v8 = qkv8 + 2 * (size_t)BATCH * SBb;    // [b][c][tok]
    const float scale = 0.0625f;

    cudaFuncSetAttribute(bgemm<4,1>, cudaFuncAttributeMaxDynamicSharedMemorySize, SMEM_B16);
    cudaFuncSetAttribute(bgemm<1,0>, cudaFuncAttributeMaxDynamicSharedMemorySize, SMEM_B16);
    cudaFuncSetAttribute(fgemm<2>,   cudaFuncAttributeMaxDynamicSharedMemorySize, SMEM_F8);
    cudaFuncSetAttribute(fgemm<3>,   cudaFuncAttributeMaxDynamicSharedMemorySize, SMEM_F8);

    // 0) convert+pack weights / biases
    convw_kernel<<<256, 256>>>(wq, wk, wv, wo, bq, bk, bv,
                               wqb, wqb + CCH*CCH, wqb + 2*CCH*CCH, wob, biasqkv);

    // 1) GroupNorm (stats + apply), bf16 out
    gn_stats_kernel<<<BATCH * GROUPS * 4, 256>>>(x, stat);
    gn_apply_kernel<<<BATCH * GROUPS * 4, 256>>>(x, stat, gn_w, gn_b, xnb);

    // 2) fused QKV projection (bf16 mainloop, fp8 outputs)
    bgemm<4,1><<<dim3(NTOK/128, 6, BATCH), 128, SMEM_B16>>>(
        wqb, xnb, biasqkv, nullptr, qkv8,
        CCH, CCH, NTOK, NTOK, 0, SBb, 0, 0);

    // 3) scores (fp8): A=q [i][c], B=k [j][c]; exp + psum; P fp8 [i][j]
    fgemm<2><<<dim3(NTOK/128, NTOK/128, BATCH), 128, SMEM_F8>>>(
        q8, k8, atb8, psum, nullptr,
        CCH, CCH, CCH, NTOK, SBb, SBb, SAb, scale);

    // 4) reduce + invert row sums
    rowinv_kernel<<<BATCH * NTOK / 256, 256>>>(psum, invs);

    // 5) PV (fp8): A=v [c][j], B=P [i][j]; normalize epilogue; bf16 out [c][i]
    fgemm<3><<<dim3(NTOK/128, CCH/128, BATCH), 128, SMEM_F8>>>(
        v8, atb8, ob, nullptr, invs,
        NTOK, NTOK, NTOK, NTOK, SBb, SAb, SBb, 1.0f);

    // 6) output projection + bias + residual (bf16 mainloop, fp32 out)
    bgemm<1,0><<<dim3(NTOK/128, CCH/128, BATCH), 128, SMEM_B16>>>(
        wob, ob, bo, x, out,
        CCH, CCH, NTOK, NTOK, 0, SBb, SBb, SBb);
}

// round 10
// speedup vs baseline: 1.1935x; 1.1935x over previous
#include <cuda_runtime.h>
#include <cuda_bf16.h>
#include <cstdint>
#include <cstddef>

#define BATCH 4
#define CCH 256
#define NTOK 4096
#define GROUPS 32
#define CPG 8
#define EPSV 1e-6f

typedef __nv_bfloat16 bf16;

// ---------------- scratch ----------------
__device__ uint4 g_xnb4 [(size_t)BATCH * CCH * NTOK / 8];
__device__ uint4 g_qkvb4[(size_t)3 * BATCH * CCH * NTOK / 8];
__device__ uint4 g_ob4  [(size_t)BATCH * CCH * NTOK / 8];
__device__ uint4 g_attnb4[(size_t)BATCH * NTOK * NTOK / 8];
__device__ uint4 g_wb4[4][CCH * CCH / 8];
__device__ float g_biasqkv[3 * CCH];
__device__ float g_psum[(size_t)BATCH * NTOK * 32];
__device__ float g_gnstat[BATCH * GROUPS * 4 * 2];

// ---------------- asm helpers ----------------
__device__ __forceinline__ uint32_t smem_u32(const void* p) {
    uint32_t a;
    asm("{ .reg .u64 t; cvta.to.shared.u64 t, %1; cvt.u32.u64 %0, t; }"
        : "=r"(a) : "l"(p));
    return a;
}
__device__ __forceinline__ void ldsm4(uint32_t* r, uint32_t a) {
    asm volatile("ldmatrix.sync.aligned.m8n8.x4.shared.b16 {%0,%1,%2,%3}, [%4];"
        : "=r"(r[0]), "=r"(r[1]), "=r"(r[2]), "=r"(r[3]) : "r"(a));
}
__device__ __forceinline__ void ldsm4t(uint32_t* r, uint32_t a) {
    asm volatile("ldmatrix.sync.aligned.m8n8.x4.trans.shared.b16 {%0,%1,%2,%3}, [%4];"
        : "=r"(r[0]), "=r"(r[1]), "=r"(r[2]), "=r"(r[3]) : "r"(a));
}
__device__ __forceinline__ void mma16(float* c, const uint32_t* a,
                                      uint32_t b0, uint32_t b1) {
    asm volatile(
        "mma.sync.aligned.m16n8k16.row.col.f32.bf16.bf16.f32 "
        "{%0,%1,%2,%3}, {%4,%5,%6,%7}, {%8,%9}, {%0,%1,%2,%3};"
        : "+f"(c[0]), "+f"(c[1]), "+f"(c[2]), "+f"(c[3])
        : "r"(a[0]), "r"(a[1]), "r"(a[2]), "r"(a[3]), "r"(b0), "r"(b1));
}
__device__ __forceinline__ void cp16(uint32_t d, const void* s) {
    asm volatile("cp.async.cg.shared.global [%0], [%1], 16;" :: "r"(d), "l"(s));
}

// ---------------------------------------------------------------------------
__global__ void convw_kernel(const float* wq, const float* wk,
                             const float* wv, const float* wo,
                             const float* bq, const float* bk, const float* bv,
                             bf16* w0, bf16* w1, bf16* w2, bf16* w3,
                             float* biasqkv) {
    int i = blockIdx.x * 256 + threadIdx.x;
    w0[i] = __float2bfloat16(wq[i]);
    w1[i] = __float2bfloat16(wk[i]);
    w2[i] = __float2bfloat16(wv[i]);
    w3[i] = __float2bfloat16(wo[i]);
    if (i < CCH) {
        biasqkv[i]           = bq[i];
        biasqkv[CCH + i]     = bk[i];
        biasqkv[2 * CCH + i] = bv[i];
    }
}

// ---------------------------------------------------------------------------
__global__ void gn_stats_kernel(const float* __restrict__ x,
                                float* __restrict__ stat) {
    const float4* xp = (const float4*)(x + (size_t)blockIdx.x * 8192);
    int tid = threadIdx.x;
    float s = 0.f, s2 = 0.f;
    #pragma unroll
    for (int i = 0; i < 8; i++) {
        float4 v = xp[tid + i * 256];
        s  += v.x + v.y + v.z + v.w;
        s2 += v.x*v.x + v.y*v.y + v.z*v.z + v.w*v.w;
    }
    __shared__ float sh0[256], sh1[256];
    sh0[tid] = s; sh1[tid] = s2;
    __syncthreads();
    for (int off = 128; off > 0; off >>= 1) {
        if (tid < off) { sh0[tid] += sh0[tid + off]; sh1[tid] += sh1[tid + off]; }
        __syncthreads();
    }
    if (tid == 0) {
        stat[blockIdx.x * 2]     = sh0[0];
        stat[blockIdx.x * 2 + 1] = sh1[0];
    }
}

__global__ void gn_apply_kernel(const float* __restrict__ x,
                                const float* __restrict__ stat,
                                const float* __restrict__ w,
                                const float* __restrict__ b,
                                bf16* __restrict__ xnb) {
    int blk = blockIdx.x;
    int bg  = blk >> 2;
    int grp = bg % GROUPS;
    float s  = stat[bg * 8 + 0] + stat[bg * 8 + 2] +
               stat[bg * 8 + 4] + stat[bg * 8 + 6];
    float s2 = stat[bg * 8 + 1] + stat[bg * 8 + 3] +
               stat[bg * 8 + 5] + stat[bg * 8 + 7];
    const float nall = (float)(CPG * NTOK);
    float mean = s / nall;
    float var  = s2 / nall - mean * mean;
    float rstd = rsqrtf(var + EPSV);

    size_t base = (size_t)blk * 8192;
    const float4* xp = (const float4*)(x + base);
    bf16* op = xnb + base;
    int tid = threadIdx.x;
    #pragma unroll
    for (int i = 0; i < 8; i++) {
        int idx = tid + i * 256;
        int ch = grp * CPG + (int)(((blk & 3) * 8192 + idx * 4) / NTOK);
        float sc = rstd * w[ch];
        float sb = b[ch] - mean * sc;
        float4 v = xp[idx];
        __nv_bfloat162 h0 = __floats2bfloat162_rn(v.x * sc + sb, v.y * sc + sb);
        __nv_bfloat162 h1 = __floats2bfloat162_rn(v.z * sc + sb, v.w * sc + sb);
        uint2 u;
        u.x = *(uint32_t*)&h0; u.y = *(uint32_t*)&h1;
        *(uint2*)(op + idx * 4) = u;
    }
}

// ---------------------------------------------------------------------------
// bf16 GEMM, CTA tile 128x128, BK=64, 128 threads = 4 warps @ 64x64.
// 3-stage cp.async ring. Epilogues:
// OUTF 0: bf16 (+bias, QKV-packed)       OUTF 1: fp32 + bias + resid
// OUTF 2: P=exp(acc*alpha), smem-staged coalesced bf16 store + psum partials
// OUTF 3: normalize by row-sum (reduced in-kernel from psum), staged store
// ---------------------------------------------------------------------------
#define ABYTES 18432u
#define STAGEB 36864u
#define SMEM_DYN (3 * 36864)

template <int AST, int BST, int OUTF, int QKV>
__global__ void __launch_bounds__(128, 2)
bgemm(const bf16* __restrict__ A, const bf16* __restrict__ B,
      const float* __restrict__ bias, const float* __restrict__ resid,
      void* __restrict__ Cv, float* __restrict__ psum,
      int K, int lda, int ldb, int ldc,
      size_t sA, size_t sB, size_t sC, size_t sR, float alpha) {
    extern __shared__ __align__(16) char smem[];
    const int bz = blockIdx.z;

    int M0;
    size_t cext = 0;
    if (QKV) {
        int mat = blockIdx.y >> 1;
        A    += (size_t)mat * (CCH * CCH);
        bias += mat * CCH;
        cext  = (size_t)mat * BATCH * (size_t)CCH * NTOK;
        M0 = (blockIdx.y & 1) * 128;
    } else {
        M0 = blockIdx.y * 128;
    }
    A += (size_t)bz * sA;
    B += (size_t)bz * sB;

    const int N0 = blockIdx.x * 128;
    const int tid  = threadIdx.x;
    const int lane = tid & 31;
    const int wid  = tid >> 5;
    const int wm = wid >> 1;
    const int wn = wid & 1;
    const int g  = lane >> 2;
    const int t  = lane & 3;
    const int l7  = lane & 7;
    const int l15 = lane & 15;
    const int b3 = (lane >> 3) & 1;
    const int b4 = (lane >> 4) & 1;

    const uint32_t smem_u = smem_u32(smem);

    float acc[4][8][4];
    #pragma unroll
    for (int i = 0; i < 4; i++)
        #pragma unroll
        for (int j = 0; j < 8; j++)
            #pragma unroll
            for (int q = 0; q < 4; q++) acc[i][j][q] = 0.f;

    const int KT = K >> 6;

    auto stage = [&](int kt, int buf) {
        uint32_t ab = smem_u + (uint32_t)buf * STAGEB;
        uint32_t bbs = ab + ABYTES;
        int k0 = kt << 6;
        #pragma unroll
        for (int i = 0; i < 8; i++) {
            int c = tid + i * 128;
            if (AST == 0) {
                int m = c >> 3, kc = c & 7;
                cp16(ab + (uint32_t)(m * 72 + kc * 8) * 2,
                     A + (size_t)(M0 + m) * lda + k0 + kc * 8);
            } else {
                int k = c >> 4, mc = c & 15;
                cp16(ab + (uint32_t)(k * 136 + mc * 8) * 2,
                     A + (size_t)(k0 + k) * lda + M0 + mc * 8);
            }
        }
        #pragma unroll
        for (int i = 0; i < 8; i++) {
            int c = tid + i * 128;
            if (BST == 0) {
                int n = c >> 3, kc = c & 7;
                cp16(bbs + (uint32_t)(n * 72 + kc * 8) * 2,
                     B + (size_t)(N0 + n) * ldb + k0 + kc * 8);
            } else {
                int k = c >> 4, nc = c & 15;
                cp16(bbs + (uint32_t)(k * 136 + nc * 8) * 2,
                     B + (size_t)(k0 + k) * ldb + N0 + nc * 8);
            }
        }
    };

    stage(0, 0);
    asm volatile("cp.async.commit_group;" ::: "memory");
    stage(1, 1);
    asm volatile("cp.async.commit_group;" ::: "memory");

    for (int kt = 0; kt < KT; kt++) {
        asm volatile("cp.async.wait_group 1;" ::: "memory");
        __syncthreads();
        if (kt + 2 < KT) stage(kt + 2, (kt + 2) % 3);
        asm volatile("cp.async.commit_group;" ::: "memory");

        uint32_t ab = smem_u + (uint32_t)(kt % 3) * STAGEB;
        uint32_t bbs = ab + ABYTES;

        #pragma unroll
        for (int ks = 0; ks < 4; ks++) {
            uint32_t af[4][4];
            #pragma unroll
            for (int i = 0; i < 4; i++) {
                if (AST == 0) {
                    uint32_t addr = ab + 2u * (uint32_t)(
                        (wm * 64 + i * 16 + l15) * 72 + ks * 16 + b4 * 8);
                    ldsm4(af[i], addr);
                } else {
                    uint32_t addr = ab + 2u * (uint32_t)(
                        (ks * 16 + b4 * 8 + l7) * 136 + wm * 64 + i * 16 + b3 * 8);
                    ldsm4t(af[i], addr);
                }
            }
            uint32_t bfr[4][4];
            #pragma unroll
            for (int j2 = 0; j2 < 4; j2++) {
                int nb = wn * 64 + j2 * 16;
                if (BST == 0) {
                    uint32_t addr = bbs + 2u * (uint32_t)(
                        (nb + b4 * 8 + l7) * 72 + ks * 16 + b3 * 8);
                    ldsm4(bfr[j2], addr);
                } else {
                    uint32_t addr = bbs + 2u * (uint32_t)(
                        (ks * 16 + b3 * 8 + l7) * 136 + nb + b4 * 8);
                    ldsm4t(bfr[j2], addr);
                }
            }
            #pragma unroll
            for (int j2 = 0; j2 < 4; j2++) {
                #pragma unroll
                for (int i = 0; i < 4; i++) {
                    mma16(acc[i][2*j2],     af[i], bfr[j2][0], bfr[j2][1]);
                    mma16(acc[i][2*j2 + 1], af[i], bfr[j2][2], bfr[j2][3]);
                }
            }
        }
    }

    // -------- epilogues --------
    if (OUTF == 0) {
        bf16* C = (bf16*)Cv + cext + (size_t)bz * sC;
        #pragma unroll
        for (int i = 0; i < 4; i++) {
            int m = M0 + wm * 64 + i * 16 + g;
            float bm0 = bias[m];
            float bm1 = bias[m + 8];
            #pragma unroll
            for (int j = 0; j < 8; j++) {
                int n = N0 + wn * 64 + j * 8 + 2 * t;
                *(__nv_bfloat162*)(C + (size_t)m * ldc + n) =
                    __floats2bfloat162_rn(acc[i][j][0] + bm0, acc[i][j][1] + bm0);
                *(__nv_bfloat162*)(C + (size_t)(m + 8) * ldc + n) =
                    __floats2bfloat162_rn(acc[i][j][2] + bm1, acc[i][j][3] + bm1);
            }
        }
    } else if (OUTF == 1) {
        float* C = (float*)Cv + (size_t)bz * sC;
        const float* R = resid + (size_t)bz * sR;
        #pragma unroll
        for (int i = 0; i < 4; i++) {
            int m = M0 + wm * 64 + i * 16 + g;
            float bm0 = bias[m];
            float bm1 = bias[m + 8];
            #pragma unroll
            for (int j = 0; j < 8; j++) {
                int n = N0 + wn * 64 + j * 8 + 2 * t;
                float2 r0 = *(const float2*)(R + (size_t)m * ldc + n);
                float2 r1 = *(const float2*)(R + (size_t)(m + 8) * ldc + n);
                float2 v0, v1;
                v0.x = acc[i][j][0] + bm0 + r0.x;
                v0.y = acc[i][j][1] + bm0 + r0.y;
                v1.x = acc[i][j][2] + bm1 + r1.x;
                v1.y = acc[i][j][3] + bm1 + r1.y;
                *(float2*)(C + (size_t)m * ldc + n)       = v0;
                *(float2*)(C + (size_t)(m + 8) * ldc + n) = v1;
            }
        }
    } else if (OUTF == 2) {
        // exp -> smem-staged coalesced bf16 store + partial row sums
        bf16* P = (bf16*)Cv + (size_t)bz * sC;
        bf16* Pt = (bf16*)smem;                       // [128][136]
        float* ps = (float*)(smem + 34816);           // [2][128]
        __syncthreads();
        #pragma unroll
        for (int i = 0; i < 4; i++) {
            int ml = wm * 64 + i * 16 + g;
            float sr0 = 0.f, sr1 = 0.f;
            #pragma unroll
            for (int j = 0; j < 8; j++) {
                int nl = wn * 64 + j * 8 + 2 * t;
                float e0 = __expf(acc[i][j][0] * alpha);
                float e1 = __expf(acc[i][j][1] * alpha);
                float e2 = __expf(acc[i][j][2] * alpha);
                float e3 = __expf(acc[i][j][3] * alpha);
                sr0 += e0 + e1;
                sr1 += e2 + e3;
                *(__nv_bfloat162*)(Pt + ml * 136 + nl) =
                    __floats2bfloat162_rn(e0, e1);
                *(__nv_bfloat162*)(Pt + (ml + 8) * 136 + nl) =
                    __floats2bfloat162_rn(e2, e3);
            }
            sr0 += __shfl_xor_sync(0xffffffffu, sr0, 1);
            sr0 += __shfl_xor_sync(0xffffffffu, sr0, 2);
            sr1 += __shfl_xor_sync(0xffffffffu, sr1, 1);
            sr1 += __shfl_xor_sync(0xffffffffu, sr1, 2);
            if (t == 0) {
                int r = wm * 64 + i * 16 + g;
                ps[wn * 128 + r]     = sr0;
                ps[wn * 128 + r + 8] = sr1;
            }
        }
        __syncthreads();
        // coalesced 16B stores: 16 lanes cover one 256B row
        int rrow = tid >> 4;     // 0..7
        int cseg = tid & 15;     // 0..15
        #pragma unroll
        for (int it = 0; it < 16; it++) {
            int r = it * 8 + rrow;
            uint4 v = *(uint4*)(Pt + r * 136 + cseg * 8);
            *(uint4*)(P + (size_t)(M0 + r) * ldc + N0 + cseg * 8) = v;
        }
        float tot = ps[tid] + ps[128 + tid];
        psum[((size_t)bz * NTOK + M0 + tid) * 32 + blockIdx.x] = tot;
    } else {
        // OUTF == 3: reduce psum in-kernel, normalize, staged coalesced store
        bf16* C = (bf16*)Cv + (size_t)bz * sC;
        bf16* Ot = (bf16*)smem;                       // [128][136]
        float* invs_s = (float*)(smem + 34816);       // [128]
        __syncthreads();
        {
            const float4* pp = (const float4*)(psum +
                ((size_t)bz * NTOK + N0 + tid) * 32);
            float s = 0.f;
            #pragma unroll
            for (int j = 0; j < 8; j++) {
                float4 a = pp[j];
                s += a.x + a.y + a.z + a.w;
            }
            invs_s[tid] = 1.f / s;
        }
        __syncthreads();
        #pragma unroll
        for (int i = 0; i < 4; i++) {
            int ml = wm * 64 + i * 16 + g;
            #pragma unroll
            for (int j = 0; j < 8; j++) {
                int nl = wn * 64 + j * 8 + 2 * t;
                float w0 = invs_s[nl];
                float w1 = invs_s[nl + 1];
                *(__nv_bfloat162*)(Ot + ml * 136 + nl) =
                    __floats2bfloat162_rn(acc[i][j][0] * w0, acc[i][j][1] * w1);
                *(__nv_bfloat162*)(Ot + (ml + 8) * 136 + nl) =
                    __floats2bfloat162_rn(acc[i][j][2] * w0, acc[i][j][3] * w1);
            }
        }
        __syncthreads();
        int rrow = tid >> 4;
        int cseg = tid & 15;
        #pragma unroll
        for (int it = 0; it < 16; it++) {
            int r = it * 8 + rrow;
            uint4 v = *(uint4*)(Ot + r * 136 + cseg * 8);
            *(uint4*)(C + (size_t)(M0 + r) * ldc + N0 + cseg * 8) = v;
        }
    }
}

// ---------------------------------------------------------------------------
extern "C" void kernel_launch(void* const* d_in, const int* in_sizes, int n_in,
                              void* d_out, int out_size) {
    const float* x    = (const float*)d_in[0];
    const float* gn_w = (const float*)d_in[1];
    const float* gn_b = (const float*)d_in[2];
    const float* wq   = (const float*)d_in[3];
    const float* bq   = (const float*)d_in[4];
    const float* wk   = (const float*)d_in[5];
    const float* bk   = (const float*)d_in[6];
    const float* wv   = (const float*)d_in[7];
    const float* bv   = (const float*)d_in[8];
    const float* wo   = (const float*)d_in[9];
    const float* bo   = (const float*)d_in[10];
    float* out = (float*)d_out;

    void *p_xn, *p_qkv, *p_o, *p_attn, *p_w, *p_bias, *p_psum, *p_stat;
    cudaGetSymbolAddress(&p_xn,   g_xnb4);
    cudaGetSymbolAddress(&p_qkv,  g_qkvb4);
    cudaGetSymbolAddress(&p_o,    g_ob4);
    cudaGetSymbolAddress(&p_attn, g_attnb4);
    cudaGetSymbolAddress(&p_w,    g_wb4);
    cudaGetSymbolAddress(&p_bias, g_biasqkv);
    cudaGetSymbolAddress(&p_psum, g_psum);
    cudaGetSymbolAddress(&p_stat, g_gnstat);

    bf16* xnb  = (bf16*)p_xn;
    bf16* qkvb = (bf16*)p_qkv;
    bf16* atb  = (bf16*)p_attn;
    bf16* ob   = (bf16*)p_o;
    bf16* wqb  = (bf16*)p_w;
    bf16* wob  = wqb + 3 * CCH * CCH;
    float* biasqkv = (float*)p_bias;
    float* psum = (float*)p_psum;
    float* stat = (float*)p_stat;

    const size_t SBb = (size_t)CCH * NTOK;
    const size_t SAb = (size_t)NTOK * NTOK;
    bf16* qb = qkvb;
    bf16* kb = qkvb + BATCH * SBb;
    bf16* vb = qkvb + 2 * BATCH * SBb;
    const float scale = 0.0625f;

    cudaFuncSetAttribute(bgemm<0,1,0,1>, cudaFuncAttributeMaxDynamicSharedMemorySize, SMEM_DYN);
    cudaFuncSetAttribute(bgemm<1,1,2,0>, cudaFuncAttributeMaxDynamicSharedMemorySize, SMEM_DYN);
    cudaFuncSetAttribute(bgemm<0,0,3,0>, cudaFuncAttributeMaxDynamicSharedMemorySize, SMEM_DYN);
    cudaFuncSetAttribute(bgemm<0,1,1,0>, cudaFuncAttributeMaxDynamicSharedMemorySize, SMEM_DYN);

    // 0) convert+pack weights / biases
    convw_kernel<<<256, 256>>>(wq, wk, wv, wo, bq, bk, bv,
                               wqb, wqb + CCH*CCH, wqb + 2*CCH*CCH, wob, biasqkv);

    // 1) GroupNorm (stats + apply), bf16 out
    gn_stats_kernel<<<BATCH * GROUPS * 4, 256>>>(x, stat);
    gn_apply_kernel<<<BATCH * GROUPS * 4, 256>>>(x, stat, gn_w, gn_b, xnb);

    // 2) fused QKV projection
    bgemm<0,1,0,1><<<dim3(NTOK/128, 6, BATCH), 128, SMEM_DYN>>>(
        wqb, xnb, biasqkv, nullptr, qkvb, nullptr,
        CCH, CCH, NTOK, NTOK, 0, SBb, SBb, 0, 1.0f);

    // 3) scores + exp + staged coalesced P store + partial row sums
    bgemm<1,1,2,0><<<dim3(NTOK/128, NTOK/128, BATCH), 128, SMEM_DYN>>>(
        qb, kb, nullptr, nullptr, atb, psum,
        CCH, NTOK, NTOK, NTOK, SBb, SBb, SAb, 0, scale);

    // 4) PV with in-kernel row-sum reduction + normalize epilogue
    bgemm<0,0,3,0><<<dim3(NTOK/128, CCH/128, BATCH), 128, SMEM_DYN>>>(
        vb, atb, nullptr, nullptr, ob, psum,
        NTOK, NTOK, NTOK, NTOK, SBb, SAb, SBb, 0, 1.0f);

    // 5) output projection + bias + residual (fp32 out)
    bgemm<0,1,1,0><<<dim3(NTOK/128, CCH/128, BATCH), 128, SMEM_DYN>>>(
        wob, ob, bo, x, out, nullptr,
        CCH, CCH, NTOK, NTOK, 0, SBb, SBb, SBb, 1.0f);
}

// round 12
// speedup vs baseline: 1.2485x; 1.0461x over previous
#include <cuda_runtime.h>
#include <cuda_bf16.h>
#include <cstdint>
#include <cstddef>

#define BATCH 4
#define CCH 256
#define NTOK 4096
#define GROUPS 32
#define CPG 8
#define EPSV 1e-6f

typedef __nv_bfloat16 bf16;

// ---------------- scratch ----------------
__device__ uint4 g_xnb4 [(size_t)BATCH * CCH * NTOK / 8];        // GN out bf16 [c][tok]
__device__ uint4 g_qkvb4[(size_t)3 * BATCH * CCH * NTOK / 8];    // q,k,v all [tok][ch] bf16
__device__ uint4 g_ob4  [(size_t)BATCH * CCH * NTOK / 8];        // O [tok][ch] bf16
__device__ uint4 g_wb4[4][CCH * CCH / 8];
__device__ float g_biasqkv[3 * CCH];
__device__ float g_gnstat[BATCH * GROUPS * 4 * 2];

// ---------------- asm helpers ----------------
__device__ __forceinline__ uint32_t smem_u32(const void* p) {
    uint32_t a;
    asm("{ .reg .u64 t; cvta.to.shared.u64 t, %1; cvt.u32.u64 %0, t; }"
        : "=r"(a) : "l"(p));
    return a;
}
__device__ __forceinline__ void ldsm4(uint32_t* r, uint32_t a) {
    asm volatile("ldmatrix.sync.aligned.m8n8.x4.shared.b16 {%0,%1,%2,%3}, [%4];"
        : "=r"(r[0]), "=r"(r[1]), "=r"(r[2]), "=r"(r[3]) : "r"(a));
}
__device__ __forceinline__ void ldsm4t(uint32_t* r, uint32_t a) {
    asm volatile("ldmatrix.sync.aligned.m8n8.x4.trans.shared.b16 {%0,%1,%2,%3}, [%4];"
        : "=r"(r[0]), "=r"(r[1]), "=r"(r[2]), "=r"(r[3]) : "r"(a));
}
__device__ __forceinline__ void mma16(float* c, const uint32_t* a,
                                      uint32_t b0, uint32_t b1) {
    asm volatile(
        "mma.sync.aligned.m16n8k16.row.col.f32.bf16.bf16.f32 "
        "{%0,%1,%2,%3}, {%4,%5,%6,%7}, {%8,%9}, {%0,%1,%2,%3};"
        : "+f"(c[0]), "+f"(c[1]), "+f"(c[2]), "+f"(c[3])
        : "r"(a[0]), "r"(a[1]), "r"(a[2]), "r"(a[3]), "r"(b0), "r"(b1));
}
__device__ __forceinline__ void cp16(uint32_t d, const void* s) {
    asm volatile("cp.async.cg.shared.global [%0], [%1], 16;" :: "r"(d), "l"(s));
}
#define CPCOMMIT asm volatile("cp.async.commit_group;" ::: "memory")
#define CPWAIT(n) asm volatile("cp.async.wait_group %0;" :: "n"(n) : "memory")

__device__ __forceinline__ uint32_t packbf(float a, float b) {
    __nv_bfloat162 h = __floats2bfloat162_rn(a, b);
    return *(uint32_t*)&h;
}

// ---------------------------------------------------------------------------
__global__ void convw_kernel(const float* wq, const float* wk,
                             const float* wv, const float* wo,
                             const float* bq, const float* bk, const float* bv,
                             bf16* w0, bf16* w1, bf16* w2, bf16* w3,
                             float* biasqkv) {
    int i = blockIdx.x * 256 + threadIdx.x;
    w0[i] = __float2bfloat16(wq[i]);
    w1[i] = __float2bfloat16(wk[i]);
    w2[i] = __float2bfloat16(wv[i]);
    w3[i] = __float2bfloat16(wo[i]);
    if (i < CCH) {
        biasqkv[i]           = bq[i];
        biasqkv[CCH + i]     = bk[i];
        biasqkv[2 * CCH + i] = bv[i];
    }
}

// ---------------------------------------------------------------------------
__global__ void gn_stats_kernel(const float* __restrict__ x,
                                float* __restrict__ stat) {
    const float4* xp = (const float4*)(x + (size_t)blockIdx.x * 8192);
    int tid = threadIdx.x;
    float s = 0.f, s2 = 0.f;
    #pragma unroll
    for (int i = 0; i < 8; i++) {
        float4 v = xp[tid + i * 256];
        s  += v.x + v.y + v.z + v.w;
        s2 += v.x*v.x + v.y*v.y + v.z*v.z + v.w*v.w;
    }
    __shared__ float sh0[256], sh1[256];
    sh0[tid] = s; sh1[tid] = s2;
    __syncthreads();
    for (int off = 128; off > 0; off >>= 1) {
        if (tid < off) { sh0[tid] += sh0[tid + off]; sh1[tid] += sh1[tid + off]; }
        __syncthreads();
    }
    if (tid == 0) {
        stat[blockIdx.x * 2]     = sh0[0];
        stat[blockIdx.x * 2 + 1] = sh1[0];
    }
}

__global__ void gn_apply_kernel(const float* __restrict__ x,
                                const float* __restrict__ stat,
                                const float* __restrict__ w,
                                const float* __restrict__ b,
                                bf16* __restrict__ xnb) {
    int blk = blockIdx.x;
    int bg  = blk >> 2;
    int grp = bg % GROUPS;
    float s  = stat[bg * 8 + 0] + stat[bg * 8 + 2] +
               stat[bg * 8 + 4] + stat[bg * 8 + 6];
    float s2 = stat[bg * 8 + 1] + stat[bg * 8 + 3] +
               stat[bg * 8 + 5] + stat[bg * 8 + 7];
    const float nall = (float)(CPG * NTOK);
    float mean = s / nall;
    float var  = s2 / nall - mean * mean;
    float rstd = rsqrtf(var + EPSV);

    size_t base = (size_t)blk * 8192;
    const float4* xp = (const float4*)(x + base);
    bf16* op = xnb + base;
    int tid = threadIdx.x;
    #pragma unroll
    for (int i = 0; i < 8; i++) {
        int idx = tid + i * 256;
        int ch = grp * CPG + (int)(((blk & 3) * 8192 + idx * 4) / NTOK);
        float sc = rstd * w[ch];
        float sb = b[ch] - mean * sc;
        float4 v = xp[idx];
        __nv_bfloat162 h0 = __floats2bfloat162_rn(v.x * sc + sb, v.y * sc + sb);
        __nv_bfloat162 h1 = __floats2bfloat162_rn(v.z * sc + sb, v.w * sc + sb);
        uint2 u;
        u.x = *(uint32_t*)&h0; u.y = *(uint32_t*)&h1;
        *(uint2*)(op + idx * 4) = u;
    }
}

// ---------------------------------------------------------------------------
// bf16 GEMM, CTA 128x128, BK=64, 128 thr = 4 warps @ 64x64, 3-stage ring.
// AST 0: A [m][k] k-cont (72)   AST 1: A [k][m] m-cont (136, .trans)
// BST 0: B [n][k] k-cont (72)   BST 1: B [k][n] n-cont (136, .trans)
// OUTF 1: fp32 + bias[m] + resid
// OUTF 5: bf16, (acc + bias[n]) * osc      (transposed-output projections)
// QKV 2: blockIdx.y = mat*32 + mtile; B/bias/C offset per mat; osc for q
// ---------------------------------------------------------------------------
#define ABYTES 18432u
#define STAGEB 36864u
#define SMEM_DYN (3 * 36864)

template <int AST, int BST, int OUTF, int QKV>
__global__ void __launch_bounds__(128, 2)
bgemm(const bf16* __restrict__ A, const bf16* __restrict__ B,
      const float* __restrict__ bias, const float* __restrict__ resid,
      void* __restrict__ Cv,
      int K, int lda, int ldb, int ldc,
      size_t sA, size_t sB, size_t sC, size_t sR) {
    extern __shared__ __align__(16) char smem[];
    const int bz = blockIdx.z;

    int M0;
    size_t cext = 0;
    float osc = 1.0f;
    if (QKV == 2) {
        int mat = blockIdx.y >> 5;             // 0=q, 1=k, 2=v
        B    += (size_t)mat * (CCH * CCH);
        bias += mat * CCH;
        cext  = (size_t)mat * BATCH * (size_t)NTOK * CCH;
        if (mat == 0) osc = 0.0625f;
        M0 = (blockIdx.y & 31) * 128;
    } else {
        M0 = blockIdx.y * 128;
    }
    A += (size_t)bz * sA;
    B += (size_t)bz * sB;

    const int N0 = blockIdx.x * 128;
    const int tid  = threadIdx.x;
    const int lane = tid & 31;
    const int wid  = tid >> 5;
    const int wm = wid >> 1;
    const int wn = wid & 1;
    const int g  = lane >> 2;
    const int t  = lane & 3;
    const int l7  = lane & 7;
    const int l15 = lane & 15;
    const int b3 = (lane >> 3) & 1;
    const int b4 = (lane >> 4) & 1;

    const uint32_t smem_u = smem_u32(smem);

    float acc[4][8][4];
    #pragma unroll
    for (int i = 0; i < 4; i++)
        #pragma unroll
        for (int j = 0; j < 8; j++)
            #pragma unroll
            for (int q = 0; q < 4; q++) acc[i][j][q] = 0.f;

    const int KT = K >> 6;

    auto stage = [&](int kt, int buf) {
        uint32_t ab = smem_u + (uint32_t)buf * STAGEB;
        uint32_t bbs = ab + ABYTES;
        int k0 = kt << 6;
        #pragma unroll
        for (int i = 0; i < 8; i++) {
            int c = tid + i * 128;
            if (AST == 0) {
                int m = c >> 3, kc = c & 7;
                cp16(ab + (uint32_t)(m * 72 + kc * 8) * 2,
                     A + (size_t)(M0 + m) * lda + k0 + kc * 8);
            } else {
                int k = c >> 4, mc = c & 15;
                cp16(ab + (uint32_t)(k * 136 + mc * 8) * 2,
                     A + (size_t)(k0 + k) * lda + M0 + mc * 8);
            }
        }
        #pragma unroll
        for (int i = 0; i < 8; i++) {
            int c = tid + i * 128;
            if (BST == 0) {
                int n = c >> 3, kc = c & 7;
                cp16(bbs + (uint32_t)(n * 72 + kc * 8) * 2,
                     B + (size_t)(N0 + n) * ldb + k0 + kc * 8);
            } else {
                int k = c >> 4, nc = c & 15;
                cp16(bbs + (uint32_t)(k * 136 + nc * 8) * 2,
                     B + (size_t)(k0 + k) * ldb + N0 + nc * 8);
            }
        }
    };

    stage(0, 0);
    CPCOMMIT;
    stage(1, 1);
    CPCOMMIT;

    for (int kt = 0; kt < KT; kt++) {
        CPWAIT(1);
        __syncthreads();
        if (kt + 2 < KT) stage(kt + 2, (kt + 2) % 3);
        CPCOMMIT;

        uint32_t ab = smem_u + (uint32_t)(kt % 3) * STAGEB;
        uint32_t bbs = ab + ABYTES;

        #pragma unroll
        for (int ks = 0; ks < 4; ks++) {
            uint32_t af[4][4];
            #pragma unroll
            for (int i = 0; i < 4; i++) {
                if (AST == 0) {
                    ldsm4(af[i], ab + 2u * (uint32_t)(
                        (wm * 64 + i * 16 + l15) * 72 + ks * 16 + b4 * 8));
                } else {
                    ldsm4t(af[i], ab + 2u * (uint32_t)(
                        (ks * 16 + b4 * 8 + l7) * 136 + wm * 64 + i * 16 + b3 * 8));
                }
            }
            uint32_t bfr[4][4];
            #pragma unroll
            for (int j2 = 0; j2 < 4; j2++) {
                int nb = wn * 64 + j2 * 16;
                if (BST == 0) {
                    ldsm4(bfr[j2], bbs + 2u * (uint32_t)(
                        (nb + b4 * 8 + l7) * 72 + ks * 16 + b3 * 8));
                } else {
                    ldsm4t(bfr[j2], bbs + 2u * (uint32_t)(
                        (ks * 16 + b3 * 8 + l7) * 136 + nb + b4 * 8));
                }
            }
            #pragma unroll
            for (int j2 = 0; j2 < 4; j2++) {
                #pragma unroll
                for (int i = 0; i < 4; i++) {
                    mma16(acc[i][2*j2],     af[i], bfr[j2][0], bfr[j2][1]);
                    mma16(acc[i][2*j2 + 1], af[i], bfr[j2][2], bfr[j2][3]);
                }
            }
        }
    }

    // -------- epilogues --------
    if (OUTF == 1) {
        float* C = (float*)Cv + (size_t)bz * sC;
        const float* R = resid + (size_t)bz * sR;
        #pragma unroll
        for (int i = 0; i < 4; i++) {
            int m = M0 + wm * 64 + i * 16 + g;
            float bm0 = bias[m];
            float bm1 = bias[m + 8];
            #pragma unroll
            for (int j = 0; j < 8; j++) {
                int n = N0 + wn * 64 + j * 8 + 2 * t;
                float2 r0 = *(const float2*)(R + (size_t)m * ldc + n);
                float2 r1 = *(const float2*)(R + (size_t)(m + 8) * ldc + n);
                float2 v0, v1;
                v0.x = acc[i][j][0] + bm0 + r0.x;
                v0.y = acc[i][j][1] + bm0 + r0.y;
                v1.x = acc[i][j][2] + bm1 + r1.x;
                v1.y = acc[i][j][3] + bm1 + r1.y;
                *(float2*)(C + (size_t)m * ldc + n)       = v0;
                *(float2*)(C + (size_t)(m + 8) * ldc + n) = v1;
            }
        }
    } else {
        // OUTF == 5: bf16 out, (acc + bias[n]) * osc
        bf16* C = (bf16*)Cv + cext + (size_t)bz * sC;
        #pragma unroll
        for (int i = 0; i < 4; i++) {
            int m = M0 + wm * 64 + i * 16 + g;
            #pragma unroll
            for (int j = 0; j < 8; j++) {
                int n = N0 + wn * 64 + j * 8 + 2 * t;
                float2 bn = *(const float2*)(bias + n);
                *(__nv_bfloat162*)(C + (size_t)m * ldc + n) =
                    __floats2bfloat162_rn((acc[i][j][0] + bn.x) * osc,
                                          (acc[i][j][1] + bn.y) * osc);
                *(__nv_bfloat162*)(C + (size_t)(m + 8) * ldc + n) =
                    __floats2bfloat162_rn((acc[i][j][2] + bn.x) * osc,
                                          (acc[i][j][3] + bn.y) * osc);
            }
        }
    }
}

// ---------------------------------------------------------------------------
// Fused attention. One CTA per (batch, 128-token i-tile); 8 warps, each owns
// 16 i-rows. Q,K,V tiles all [128 rows][256 cols] bf16, stride 264, smem.
// Pipeline invariant: entering iter j, pending commit groups = {K[j], V[j]}.
// MMA1: S(m16 x n128) = Q·K^T; exp -> A-fragments in registers (no P smem);
// MMA2: O(m16 x n256) += P·V.
// ---------------------------------------------------------------------------
#define QOFF 0u
#define KOFF 67584u
#define VOFF 135168u
#define SMOFF 202752u
#define FSMEM 203264

__global__ void __launch_bounds__(256, 1)
fattn(const bf16* __restrict__ q, const bf16* __restrict__ k,
      const bf16* __restrict__ vt, bf16* __restrict__ obt) {
    extern __shared__ __align__(16) char smem[];
    const int bz = blockIdx.y;
    const int i0 = blockIdx.x * 128;
    q   += (size_t)bz * NTOK * CCH;
    k   += (size_t)bz * NTOK * CCH;
    vt  += (size_t)bz * NTOK * CCH;
    obt += (size_t)bz * NTOK * CCH;

    const int tid = threadIdx.x;
    const int lane = tid & 31;
    const int wid  = tid >> 5;        // 0..7 -> i-rows wid*16..+15
    const int g  = lane >> 2;
    const int t  = lane & 3;
    const int l7  = lane & 7;
    const int l15 = lane & 15;
    const int b3 = (lane >> 3) & 1;
    const int b4 = (lane >> 4) & 1;
    const uint32_t su = smem_u32(smem);

    float O[32][4];
    #pragma unroll
    for (int b = 0; b < 32; b++)
        #pragma unroll
        for (int qq = 0; qq < 4; qq++) O[b][qq] = 0.f;
    float rs0 = 0.f, rs1 = 0.f;

    // stage a [128][256] bf16 tile (stride 264) from row-major [row][CCH] gmem
    auto stageT = [&](uint32_t off, const bf16* src) {
        #pragma unroll
        for (int i = 0; i < 16; i++) {
            int cc = tid + i * 256;
            int r = cc >> 5, c8 = cc & 31;
            cp16(su + off + (uint32_t)(r * 264 + c8 * 8) * 2,
                 src + (size_t)r * CCH + c8 * 8);
        }
    };

    stageT(QOFF, q + (size_t)i0 * CCH); CPCOMMIT;
    stageT(KOFF, k);                    CPCOMMIT;
    stageT(VOFF, vt);                   CPCOMMIT;
    // pending: {Q, K0, V0}

    for (int j = 0; j < 32; j++) {
        CPWAIT(1);            // j=0: completes Q,K0 ; j>0: completes K[j]
        __syncthreads();

        // ---- MMA1: S[16][128] ----
        float S[16][4];
        #pragma unroll
        for (int b = 0; b < 16; b++)
            #pragma unroll
            for (int qq = 0; qq < 4; qq++) S[b][qq] = 0.f;

        #pragma unroll
        for (int ks = 0; ks < 16; ks++) {
            uint32_t a[4];
            ldsm4(a, su + QOFF + 2u * (uint32_t)(
                (wid * 16 + l15) * 264 + ks * 16 + b4 * 8));
            #pragma unroll
            for (int j2 = 0; j2 < 8; j2++) {
                uint32_t bfr[4];
                ldsm4(bfr, su + KOFF + 2u * (uint32_t)(
                    (j2 * 16 + b4 * 8 + l7) * 264 + ks * 16 + b3 * 8));
                mma16(S[2*j2],     a, bfr[0], bfr[1]);
                mma16(S[2*j2 + 1], a, bfr[2], bfr[3]);
            }
        }

        // ---- exp -> A-fragments (registers) + row sums ----
        uint32_t af2[8][4];
        #pragma unroll
        for (int b = 0; b < 8; b++) {
            float e00 = __expf(S[2*b][0]);
            float e01 = __expf(S[2*b][1]);
            float e02 = __expf(S[2*b][2]);
            float e03 = __expf(S[2*b][3]);
            float e10 = __expf(S[2*b+1][0]);
            float e11 = __expf(S[2*b+1][1]);
            float e12 = __expf(S[2*b+1][2]);
            float e13 = __expf(S[2*b+1][3]);
            rs0 += e00 + e01 + e10 + e11;
            rs1 += e02 + e03 + e12 + e13;
            af2[b][0] = packbf(e00, e01);
            af2[b][1] = packbf(e02, e03);
            af2[b][2] = packbf(e10, e11);
            af2[b][3] = packbf(e12, e13);
        }

        __syncthreads();                       // all K[j] reads done
        if (j < 31) {
            stageT(KOFF, k + (size_t)(j + 1) * 128 * CCH);
            CPCOMMIT;                          // pending: {V[j], K[j+1]}
            CPWAIT(1);                         // completes V[j]
        } else {
            CPWAIT(0);                         // completes V[31]
        }
        __syncthreads();                       // V[j] visible to all

        // ---- MMA2: O += P · V ----
        #pragma unroll
        for (int ks2 = 0; ks2 < 8; ks2++) {
            #pragma unroll
            for (int j2 = 0; j2 < 16; j2++) {
                uint32_t bfr[4];
                ldsm4t(bfr, su + VOFF + 2u * (uint32_t)(
                    (ks2 * 16 + b3 * 8 + l7) * 264 + j2 * 16 + b4 * 8));
                mma16(O[2*j2],     af2[ks2], bfr[0], bfr[1]);
                mma16(O[2*j2 + 1], af2[ks2], bfr[2], bfr[3]);
            }
        }
        __syncthreads();                       // all V[j] reads done
        if (j < 31) {
            stageT(VOFF, vt + (size_t)(j + 1) * 128 * CCH);
            CPCOMMIT;                          // pending: {K[j+1], V[j+1]}
        }
    }

    // ---- row sums -> inverse, normalize, staged coalesced store ----
    float* sums = (float*)(smem + SMOFF);
    rs0 += __shfl_xor_sync(0xffffffffu, rs0, 1);
    rs0 += __shfl_xor_sync(0xffffffffu, rs0, 2);
    rs1 += __shfl_xor_sync(0xffffffffu, rs1, 1);
    rs1 += __shfl_xor_sync(0xffffffffu, rs1, 2);
    if (t == 0) {
        sums[wid * 16 + g]     = 1.f / rs0;
        sums[wid * 16 + 8 + g] = 1.f / rs1;
    }
    __syncthreads();

    bf16* Os = (bf16*)smem;          // reuse Q region: [128][264]
    {
        int r0 = wid * 16 + g;
        int r1 = r0 + 8;
        float iv0 = sums[r0];
        float iv1 = sums[r1];
        #pragma unroll
        for (int b = 0; b < 32; b++) {
            int col = b * 8 + 2 * t;
            *(__nv_bfloat162*)(Os + r0 * 264 + col) =
                __floats2bfloat162_rn(O[b][0] * iv0, O[b][1] * iv0);
            *(__nv_bfloat162*)(Os + r1 * 264 + col) =
                __floats2bfloat162_rn(O[b][2] * iv1, O[b][3] * iv1);
        }
    }
    __syncthreads();
    #pragma unroll
    for (int p = 0; p < 16; p++) {
        int r = p * 8 + (tid >> 5);
        int u = tid & 31;
        uint4 v = *(uint4*)(Os + r * 264 + u * 8);
        *(uint4*)(obt + (size_t)(i0 + r) * CCH + u * 8) = v;
    }
}

// ---------------------------------------------------------------------------
extern "C" void kernel_launch(void* const* d_in, const int* in_sizes, int n_in,
                              void* d_out, int out_size) {
    const float* x    = (const float*)d_in[0];
    const float* gn_w = (const float*)d_in[1];
    const float* gn_b = (const float*)d_in[2];
    const float* wq   = (const float*)d_in[3];
    const float* bq   = (const float*)d_in[4];
    const float* wk   = (const float*)d_in[5];
    const float* bk   = (const float*)d_in[6];
    const float* wv   = (const float*)d_in[7];
    const float* bv   = (const float*)d_in[8];
    const float* wo   = (const float*)d_in[9];
    const float* bo   = (const float*)d_in[10];
    float* out = (float*)d_out;

    void *p_xn, *p_qkv, *p_o, *p_w, *p_bias, *p_stat;
    cudaGetSymbolAddress(&p_xn,   g_xnb4);
    cudaGetSymbolAddress(&p_qkv,  g_qkvb4);
    cudaGetSymbolAddress(&p_o,    g_ob4);
    cudaGetSymbolAddress(&p_w,    g_wb4);
    cudaGetSymbolAddress(&p_bias, g_biasqkv);
    cudaGetSymbolAddress(&p_stat, g_gnstat);

    bf16* xnb  = (bf16*)p_xn;
    bf16* qkvb = (bf16*)p_qkv;
    bf16* obt  = (bf16*)p_o;
    bf16* wqb  = (bf16*)p_w;
    bf16* wob  = wqb + 3 * CCH * CCH;
    float* biasqkv = (float*)p_bias;
    float* stat = (float*)p_stat;

    const size_t SBb = (size_t)CCH * NTOK;     // per-batch elements
    bf16* qb  = qkvb;                           // [tok][ch]
    bf16* kb  = qkvb + BATCH * SBb;             // [tok][ch]
    bf16* vtb = qkvb + 2 * BATCH * SBb;         // [tok][ch]

    cudaFuncSetAttribute(bgemm<1,0,5,2>, cudaFuncAttributeMaxDynamicSharedMemorySize, SMEM_DYN);
    cudaFuncSetAttribute(bgemm<0,0,1,0>, cudaFuncAttributeMaxDynamicSharedMemorySize, SMEM_DYN);
    cudaFuncSetAttribute(fattn, cudaFuncAttributeMaxDynamicSharedMemorySize, FSMEM);

    // 0) convert+pack weights / biases
    convw_kernel<<<256, 256>>>(wq, wk, wv, wo, bq, bk, bv,
                               wqb, wqb + CCH*CCH, wqb + 2*CCH*CCH, wob, biasqkv);

    // 1) GroupNorm (stats + apply), bf16 out [c][tok]
    gn_stats_kernel<<<BATCH * GROUPS * 4, 256>>>(x, stat);
    gn_apply_kernel<<<BATCH * GROUPS * 4, 256>>>(x, stat, gn_w, gn_b, xnb);

    // 2) q,k,v transposed projections: [tok][ch] = xn^T·W^T + b (q scaled 1/16)
    //    grid.y = mat*32 + token-tile
    bgemm<1,0,5,2><<<dim3(CCH/128, 96, BATCH), 128, SMEM_DYN>>>(
        xnb, wqb, biasqkv, nullptr, qkvb,
        CCH, NTOK, CCH, CCH, SBb, 0, (size_t)NTOK * CCH, 0);

    // 3) fused attention -> O [tok][ch]
    fattn<<<dim3(NTOK/128, BATCH), 256, FSMEM>>>(qb, kb, vtb, obt);

    // 4) output projection + bias + residual (A=Wo [m][k], B=O [n=tok][k=ch])
    bgemm<0,0,1,0><<<dim3(NTOK/128, CCH/128, BATCH), 128, SMEM_DYN>>>(
        wob, obt, bo, x, out,
        CCH, CCH, CCH, NTOK, 0, (size_t)NTOK * CCH, SBb, SBb);
}

// round 13
// speedup vs baseline: 1.2835x; 1.0280x over previous
#include <cuda_runtime.h>
#include <cuda_bf16.h>
#include <cstdint>
#include <cstddef>

#define BATCH 4
#define CCH 256
#define NTOK 4096
#define GROUPS 32
#define CPG 8
#define EPSV 1e-6f

typedef __nv_bfloat16 bf16;

// ---------------- scratch ----------------
__device__ uint4 g_xnb4 [(size_t)BATCH * CCH * NTOK / 8];        // GN out bf16 [c][tok]
__device__ uint4 g_qkvb4[(size_t)3 * BATCH * CCH * NTOK / 8];    // q,k,v all [tok][ch] bf16
__device__ uint4 g_wb4[4][CCH * CCH / 8];
__device__ float g_biasqkv[3 * CCH];
__device__ float g_gnstat[BATCH * GROUPS * 4 * 2];

// ---------------- asm helpers ----------------
__device__ __forceinline__ uint32_t smem_u32(const void* p) {
    uint32_t a;
    asm("{ .reg .u64 t; cvta.to.shared.u64 t, %1; cvt.u32.u64 %0, t; }"
        : "=r"(a) : "l"(p));
    return a;
}
__device__ __forceinline__ void ldsm4(uint32_t* r, uint32_t a) {
    asm volatile("ldmatrix.sync.aligned.m8n8.x4.shared.b16 {%0,%1,%2,%3}, [%4];"
        : "=r"(r[0]), "=r"(r[1]), "=r"(r[2]), "=r"(r[3]) : "r"(a));
}
__device__ __forceinline__ void ldsm4t(uint32_t* r, uint32_t a) {
    asm volatile("ldmatrix.sync.aligned.m8n8.x4.trans.shared.b16 {%0,%1,%2,%3}, [%4];"
        : "=r"(r[0]), "=r"(r[1]), "=r"(r[2]), "=r"(r[3]) : "r"(a));
}
__device__ __forceinline__ void mma16(float* c, const uint32_t* a,
                                      uint32_t b0, uint32_t b1) {
    asm volatile(
        "mma.sync.aligned.m16n8k16.row.col.f32.bf16.bf16.f32 "
        "{%0,%1,%2,%3}, {%4,%5,%6,%7}, {%8,%9}, {%0,%1,%2,%3};"
        : "+f"(c[0]), "+f"(c[1]), "+f"(c[2]), "+f"(c[3])
        : "r"(a[0]), "r"(a[1]), "r"(a[2]), "r"(a[3]), "r"(b0), "r"(b1));
}
__device__ __forceinline__ void cp16(uint32_t d, const void* s) {
    asm volatile("cp.async.cg.shared.global [%0], [%1], 16;" :: "r"(d), "l"(s));
}
#define CPCOMMIT asm volatile("cp.async.commit_group;" ::: "memory")
#define CPWAIT(n) asm volatile("cp.async.wait_group %0;" :: "n"(n) : "memory")

__device__ __forceinline__ uint32_t packbf(float a, float b) {
    __nv_bfloat162 h = __floats2bfloat162_rn(a, b);
    return *(uint32_t*)&h;
}

// ---------------------------------------------------------------------------
__global__ void convw_kernel(const float* wq, const float* wk,
                             const float* wv, const float* wo,
                             const float* bq, const float* bk, const float* bv,
                             bf16* w0, bf16* w1, bf16* w2, bf16* w3,
                             float* biasqkv) {
    int i = blockIdx.x * 256 + threadIdx.x;
    w0[i] = __float2bfloat16(wq[i]);
    w1[i] = __float2bfloat16(wk[i]);
    w2[i] = __float2bfloat16(wv[i]);
    w3[i] = __float2bfloat16(wo[i]);
    if (i < CCH) {
        biasqkv[i]           = bq[i];
        biasqkv[CCH + i]     = bk[i];
        biasqkv[2 * CCH + i] = bv[i];
    }
}

// ---------------------------------------------------------------------------
__global__ void gn_stats_kernel(const float* __restrict__ x,
                                float* __restrict__ stat) {
    const float4* xp = (const float4*)(x + (size_t)blockIdx.x * 8192);
    int tid = threadIdx.x;
    float s = 0.f, s2 = 0.f;
    #pragma unroll
    for (int i = 0; i < 8; i++) {
        float4 v = xp[tid + i * 256];
        s  += v.x + v.y + v.z + v.w;
        s2 += v.x*v.x + v.y*v.y + v.z*v.z + v.w*v.w;
    }
    __shared__ float sh0[256], sh1[256];
    sh0[tid] = s; sh1[tid] = s2;
    __syncthreads();
    for (int off = 128; off > 0; off >>= 1) {
        if (tid < off) { sh0[tid] += sh0[tid + off]; sh1[tid] += sh1[tid + off]; }
        __syncthreads();
    }
    if (tid == 0) {
        stat[blockIdx.x * 2]     = sh0[0];
        stat[blockIdx.x * 2 + 1] = sh1[0];
    }
}

__global__ void gn_apply_kernel(const float* __restrict__ x,
                                const float* __restrict__ stat,
                                const float* __restrict__ w,
                                const float* __restrict__ b,
                                bf16* __restrict__ xnb) {
    int blk = blockIdx.x;
    int bg  = blk >> 2;
    int grp = bg % GROUPS;
    float s  = stat[bg * 8 + 0] + stat[bg * 8 + 2] +
               stat[bg * 8 + 4] + stat[bg * 8 + 6];
    float s2 = stat[bg * 8 + 1] + stat[bg * 8 + 3] +
               stat[bg * 8 + 5] + stat[bg * 8 + 7];
    const float nall = (float)(CPG * NTOK);
    float mean = s / nall;
    float var  = s2 / nall - mean * mean;
    float rstd = rsqrtf(var + EPSV);

    size_t base = (size_t)blk * 8192;
    const float4* xp = (const float4*)(x + base);
    bf16* op = xnb + base;
    int tid = threadIdx.x;
    #pragma unroll
    for (int i = 0; i < 8; i++) {
        int idx = tid + i * 256;
        int ch = grp * CPG + (int)(((blk & 3) * 8192 + idx * 4) / NTOK);
        float sc = rstd * w[ch];
        float sb = b[ch] - mean * sc;
        float4 v = xp[idx];
        __nv_bfloat162 h0 = __floats2bfloat162_rn(v.x * sc + sb, v.y * sc + sb);
        __nv_bfloat162 h1 = __floats2bfloat162_rn(v.z * sc + sb, v.w * sc + sb);
        uint2 u;
        u.x = *(uint32_t*)&h0; u.y = *(uint32_t*)&h1;
        *(uint2*)(op + idx * 4) = u;
    }
}

// ---------------------------------------------------------------------------
// bf16 GEMM (QKV transposed projections only now).
// CTA 128x128, BK=64, 128 thr = 4 warps @ 64x64, 3-stage ring.
// AST 1: A [k][m] m-cont (136, .trans)   BST 0: B [n][k] k-cont (72)
// OUTF 5 + QKV 2: bf16 out, (acc + bias[n]) * osc; blockIdx.y = mat*32+mtile
// ---------------------------------------------------------------------------
#define ABYTES 18432u
#define STAGEB 36864u
#define SMEM_DYN (3 * 36864)

__global__ void __launch_bounds__(128, 2)
bgemm_qkv(const bf16* __restrict__ A, const bf16* __restrict__ B,
          const float* __restrict__ bias, void* __restrict__ Cv,
          int lda, size_t sA) {
    extern __shared__ __align__(16) char smem[];
    const int bz = blockIdx.z;

    int mat = blockIdx.y >> 5;
    B    += (size_t)mat * (CCH * CCH);
    bias += mat * CCH;
    size_t cext = (size_t)mat * BATCH * (size_t)NTOK * CCH;
    float osc = (mat == 0) ? 0.0625f : 1.0f;
    const int M0 = (blockIdx.y & 31) * 128;
    A += (size_t)bz * sA;

    const int N0 = blockIdx.x * 128;
    const int tid  = threadIdx.x;
    const int lane = tid & 31;
    const int wid  = tid >> 5;
    const int wm = wid >> 1;
    const int wn = wid & 1;
    const int g  = lane >> 2;
    const int t  = lane & 3;
    const int l7  = lane & 7;
    const int b3 = (lane >> 3) & 1;
    const int b4 = (lane >> 4) & 1;

    const uint32_t smem_u = smem_u32(smem);

    float acc[4][8][4];
    #pragma unroll
    for (int i = 0; i < 4; i++)
        #pragma unroll
        for (int j = 0; j < 8; j++)
            #pragma unroll
            for (int q = 0; q < 4; q++) acc[i][j][q] = 0.f;

    const int KT = CCH >> 6;   // 4

    auto stage = [&](int kt, int buf) {
        uint32_t ab = smem_u + (uint32_t)buf * STAGEB;
        uint32_t bbs = ab + ABYTES;
        int k0 = kt << 6;
        #pragma unroll
        for (int i = 0; i < 8; i++) {
            int c = tid + i * 128;
            int k = c >> 4, mc = c & 15;
            cp16(ab + (uint32_t)(k * 136 + mc * 8) * 2,
                 A + (size_t)(k0 + k) * lda + M0 + mc * 8);
        }
        #pragma unroll
        for (int i = 0; i < 8; i++) {
            int c = tid + i * 128;
            int n = c >> 3, kc = c & 7;
            cp16(bbs + (uint32_t)(n * 72 + kc * 8) * 2,
                 B + (size_t)(N0 + n) * CCH + k0 + kc * 8);
        }
    };

    stage(0, 0);
    CPCOMMIT;
    stage(1, 1);
    CPCOMMIT;

    for (int kt = 0; kt < KT; kt++) {
        CPWAIT(1);
        __syncthreads();
        if (kt + 2 < KT) stage(kt + 2, (kt + 2) % 3);
        CPCOMMIT;

        uint32_t ab = smem_u + (uint32_t)(kt % 3) * STAGEB;
        uint32_t bbs = ab + ABYTES;

        #pragma unroll
        for (int ks = 0; ks < 4; ks++) {
            uint32_t af[4][4];
            #pragma unroll
            for (int i = 0; i < 4; i++)
                ldsm4t(af[i], ab + 2u * (uint32_t)(
                    (ks * 16 + b4 * 8 + l7) * 136 + wm * 64 + i * 16 + b3 * 8));
            uint32_t bfr[4][4];
            #pragma unroll
            for (int j2 = 0; j2 < 4; j2++) {
                int nb = wn * 64 + j2 * 16;
                ldsm4(bfr[j2], bbs + 2u * (uint32_t)(
                    (nb + b4 * 8 + l7) * 72 + ks * 16 + b3 * 8));
            }
            #pragma unroll
            for (int j2 = 0; j2 < 4; j2++) {
                #pragma unroll
                for (int i = 0; i < 4; i++) {
                    mma16(acc[i][2*j2],     af[i], bfr[j2][0], bfr[j2][1]);
                    mma16(acc[i][2*j2 + 1], af[i], bfr[j2][2], bfr[j2][3]);
                }
            }
        }
    }

    bf16* C = (bf16*)Cv + cext + (size_t)bz * NTOK * CCH;
    #pragma unroll
    for (int i = 0; i < 4; i++) {
        int m = M0 + wm * 64 + i * 16 + g;
        #pragma unroll
        for (int j = 0; j < 8; j++) {
            int n = N0 + wn * 64 + j * 8 + 2 * t;
            float2 bn = *(const float2*)(bias + n);
            *(__nv_bfloat162*)(C + (size_t)m * CCH + n) =
                __floats2bfloat162_rn((acc[i][j][0] + bn.x) * osc,
                                      (acc[i][j][1] + bn.y) * osc);
            *(__nv_bfloat162*)(C + (size_t)(m + 8) * CCH + n) =
                __floats2bfloat162_rn((acc[i][j][2] + bn.x) * osc,
                                      (acc[i][j][3] + bn.y) * osc);
        }
    }
}

// ---------------------------------------------------------------------------
// Fused attention + output projection + residual.
// One CTA per (batch, 128-token i-tile); 8 warps, each owns 16 i-rows.
// Main loop (32 j-tiles): MMA1 S=Q·K^T -> exp -> reg A-fragments; MMA2 O+=P·V.
// Pipeline invariant: entering iter j, pending = {K[j], V[j]}.
// Epilogue: normalize O -> smem; Wo (staged during last iter into K+V space);
// GEMM out[co][tok] = Wo·O^T + bo + x, fp32 direct to d_out.
// ---------------------------------------------------------------------------
#define QOFF 0u
#define KOFF 67584u
#define VOFF 135168u
#define SMOFF 202752u
#define FSMEM 203264

__global__ void __launch_bounds__(256, 1)
fattn(const bf16* __restrict__ q, const bf16* __restrict__ k,
      const bf16* __restrict__ vt, const bf16* __restrict__ wo,
      const float* __restrict__ bo, const float* __restrict__ x,
      float* __restrict__ out) {
    extern __shared__ __align__(16) char smem[];
    const int bz = blockIdx.y;
    const int i0 = blockIdx.x * 128;
    q   += (size_t)bz * NTOK * CCH;
    k   += (size_t)bz * NTOK * CCH;
    vt  += (size_t)bz * NTOK * CCH;
    x   += (size_t)bz * CCH * NTOK;
    out += (size_t)bz * CCH * NTOK;

    const int tid = threadIdx.x;
    const int lane = tid & 31;
    const int wid  = tid >> 5;
    const int g  = lane >> 2;
    const int t  = lane & 3;
    const int l7  = lane & 7;
    const int l15 = lane & 15;
    const int b3 = (lane >> 3) & 1;
    const int b4 = (lane >> 4) & 1;
    const uint32_t su = smem_u32(smem);

    float O[32][4];
    #pragma unroll
    for (int b = 0; b < 32; b++)
        #pragma unroll
        for (int qq = 0; qq < 4; qq++) O[b][qq] = 0.f;
    float rs0 = 0.f, rs1 = 0.f;

    auto stageT = [&](uint32_t off, const bf16* src) {
        #pragma unroll
        for (int i = 0; i < 16; i++) {
            int cc = tid + i * 256;
            int r = cc >> 5, c8 = cc & 31;
            cp16(su + off + (uint32_t)(r * 264 + c8 * 8) * 2,
                 src + (size_t)r * CCH + c8 * 8);
        }
    };
    // Wo [co][ch]: rows 0-127 -> KOFF, rows 128-255 -> VOFF, stride 264
    auto stageWo = [&]() {
        #pragma unroll
        for (int i = 0; i < 32; i++) {
            int cc = tid + i * 256;
            int r = cc >> 5, c8 = cc & 31;
            uint32_t dst = (r < 128)
                ? (KOFF + (uint32_t)(r * 264 + c8 * 8) * 2)
                : (VOFF + (uint32_t)((r - 128) * 264 + c8 * 8) * 2);
            cp16(su + dst, wo + (size_t)r * CCH + c8 * 8);
        }
    };

    stageT(QOFF, q + (size_t)i0 * CCH); CPCOMMIT;
    stageT(KOFF, k);                    CPCOMMIT;
    stageT(VOFF, vt);                   CPCOMMIT;
    // pending: {Q, K0, V0}

    for (int j = 0; j < 32; j++) {
        CPWAIT(1);            // j=0: completes Q,K0 ; j>0: completes K[j]
        __syncthreads();

        // ---- MMA1: S[16][128] ----
        float S[16][4];
        #pragma unroll
        for (int b = 0; b < 16; b++)
            #pragma unroll
            for (int qq = 0; qq < 4; qq++) S[b][qq] = 0.f;

        #pragma unroll
        for (int ks = 0; ks < 16; ks++) {
            uint32_t a[4];
            ldsm4(a, su + QOFF + 2u * (uint32_t)(
                (wid * 16 + l15) * 264 + ks * 16 + b4 * 8));
            #pragma unroll
            for (int j2 = 0; j2 < 8; j2++) {
                uint32_t bfr[4];
                ldsm4(bfr, su + KOFF + 2u * (uint32_t)(
                    (j2 * 16 + b4 * 8 + l7) * 264 + ks * 16 + b3 * 8));
                mma16(S[2*j2],     a, bfr[0], bfr[1]);
                mma16(S[2*j2 + 1], a, bfr[2], bfr[3]);
            }
        }

        // ---- exp -> A-fragments (registers) + row sums ----
        uint32_t af2[8][4];
        #pragma unroll
        for (int b = 0; b < 8; b++) {
            float e00 = __expf(S[2*b][0]);
            float e01 = __expf(S[2*b][1]);
            float e02 = __expf(S[2*b][2]);
            float e03 = __expf(S[2*b][3]);
            float e10 = __expf(S[2*b+1][0]);
            float e11 = __expf(S[2*b+1][1]);
            float e12 = __expf(S[2*b+1][2]);
            float e13 = __expf(S[2*b+1][3]);
            rs0 += e00 + e01 + e10 + e11;
            rs1 += e02 + e03 + e12 + e13;
            af2[b][0] = packbf(e00, e01);
            af2[b][1] = packbf(e02, e03);
            af2[b][2] = packbf(e10, e11);
            af2[b][3] = packbf(e12, e13);
        }

        __syncthreads();                       // all K[j] reads done
        if (j < 31) {
            stageT(KOFF, k + (size_t)(j + 1) * 128 * CCH);
            CPCOMMIT;                          // pending: {V[j], K[j+1]}
            CPWAIT(1);                         // completes V[j]
        } else {
            CPWAIT(0);                         // completes V[31]
        }
        __syncthreads();                       // V[j] visible to all

        // ---- MMA2: O += P · V ----
        #pragma unroll
        for (int ks2 = 0; ks2 < 8; ks2++) {
            #pragma unroll
            for (int j2 = 0; j2 < 16; j2++) {
                uint32_t bfr[4];
                ldsm4t(bfr, su + VOFF + 2u * (uint32_t)(
                    (ks2 * 16 + b3 * 8 + l7) * 264 + j2 * 16 + b4 * 8));
                mma16(O[2*j2],     af2[ks2], bfr[0], bfr[1]);
                mma16(O[2*j2 + 1], af2[ks2], bfr[2], bfr[3]);
            }
        }
        __syncthreads();                       // all K/V[j] reads done
        if (j < 31) {
            stageT(VOFF, vt + (size_t)(j + 1) * 128 * CCH);
            CPCOMMIT;                          // pending: {K[j+1], V[j+1]}
        } else {
            stageWo();                          // K/V regions now dead
            CPCOMMIT;                           // pending: {Wo}
        }
    }

    // ---- row sums -> inverse; normalize O into Q-region smem ----
    float* sums = (float*)(smem + SMOFF);
    rs0 += __shfl_xor_sync(0xffffffffu, rs0, 1);
    rs0 += __shfl_xor_sync(0xffffffffu, rs0, 2);
    rs1 += __shfl_xor_sync(0xffffffffu, rs1, 1);
    rs1 += __shfl_xor_sync(0xffffffffu, rs1, 2);
    if (t == 0) {
        sums[wid * 16 + g]     = 1.f / rs0;
        sums[wid * 16 + 8 + g] = 1.f / rs1;
    }
    __syncthreads();

    bf16* Os = (bf16*)smem;          // [128 tok][264], Q-region reuse
    {
        int r0 = wid * 16 + g;
        int r1 = r0 + 8;
        float iv0 = sums[r0];
        float iv1 = sums[r1];
        #pragma unroll
        for (int b = 0; b < 32; b++) {
            int col = b * 8 + 2 * t;
            *(__nv_bfloat162*)(Os + r0 * 264 + col) =
                __floats2bfloat162_rn(O[b][0] * iv0, O[b][1] * iv0);
            *(__nv_bfloat162*)(Os + r1 * 264 + col) =
                __floats2bfloat162_rn(O[b][2] * iv1, O[b][3] * iv1);
        }
    }
    CPWAIT(0);          // Wo staged
    __syncthreads();    // Os + Wo visible to all

    // ---- epilogue GEMM: out[256 co][128 tok] = Wo · O^T + bo + x ----
    float acc[2][16][4];
    #pragma unroll
    for (int i = 0; i < 2; i++)
        #pragma unroll
        for (int j = 0; j < 16; j++)
            #pragma unroll
            for (int qq = 0; qq < 4; qq++) acc[i][j][qq] = 0.f;

    const uint32_t wbase = (wid < 4) ? KOFF : VOFF;
    const int mrow = (wid & 3) * 32;

    #pragma unroll
    for (int ks = 0; ks < 16; ks++) {
        uint32_t a2[2][4];
        #pragma unroll
        for (int i = 0; i < 2; i++)
            ldsm4(a2[i], su + wbase + 2u * (uint32_t)(
                (mrow + i * 16 + l15) * 264 + ks * 16 + b4 * 8));
        #pragma unroll
        for (int j2 = 0; j2 < 8; j2++) {
            uint32_t bfr[4];
            ldsm4(bfr, su + QOFF + 2u * (uint32_t)(
                (j2 * 16 + b4 * 8 + l7) * 264 + ks * 16 + b3 * 8));
            #pragma unroll
            for (int i = 0; i < 2; i++) {
                mma16(acc[i][2*j2],     a2[i], bfr[0], bfr[1]);
                mma16(acc[i][2*j2 + 1], a2[i], bfr[2], bfr[3]);
            }
        }
    }

    #pragma unroll
    for (int i = 0; i < 2; i++) {
        int m = wid * 32 + i * 16 + g;          // output channel
        float bm0 = bo[m];
        float bm1 = bo[m + 8];
        #pragma unroll
        for (int j = 0; j < 16; j++) {
            int n = i0 + j * 8 + 2 * t;         // token
            float2 x0 = *(const float2*)(x + (size_t)m * NTOK + n);
            float2 x1 = *(const float2*)(x + (size_t)(m + 8) * NTOK + n);
            float2 v0, v1;
            v0.x = acc[i][j][0] + bm0 + x0.x;
            v0.y = acc[i][j][1] + bm0 + x0.y;
            v1.x = acc[i][j][2] + bm1 + x1.x;
            v1.y = acc[i][j][3] + bm1 + x1.y;
            *(float2*)(out + (size_t)m * NTOK + n)       = v0;
            *(float2*)(out + (size_t)(m + 8) * NTOK + n) = v1;
        }
    }
}

// ---------------------------------------------------------------------------
extern "C" void kernel_launch(void* const* d_in, const int* in_sizes, int n_in,
                              void* d_out, int out_size) {
    const float* x    = (const float*)d_in[0];
    const float* gn_w = (const float*)d_in[1];
    const float* gn_b = (const float*)d_in[2];
    const float* wq   = (const float*)d_in[3];
    const float* bq   = (const float*)d_in[4];
    const float* wk   = (const float*)d_in[5];
    const float* bk   = (const float*)d_in[6];
    const float* wv   = (const float*)d_in[7];
    const float* bv   = (const float*)d_in[8];
    const float* wo   = (const float*)d_in[9];
    const float* bo   = (const float*)d_in[10];
    float* out = (float*)d_out;

    void *p_xn, *p_qkv, *p_w, *p_bias, *p_stat;
    cudaGetSymbolAddress(&p_xn,   g_xnb4);
    cudaGetSymbolAddress(&p_qkv,  g_qkvb4);
    cudaGetSymbolAddress(&p_w,    g_wb4);
    cudaGetSymbolAddress(&p_bias, g_biasqkv);
    cudaGetSymbolAddress(&p_stat, g_gnstat);

    bf16* xnb  = (bf16*)p_xn;
    bf16* qkvb = (bf16*)p_qkv;
    bf16* wqb  = (bf16*)p_w;
    bf16* wob  = wqb + 3 * CCH * CCH;
    float* biasqkv = (float*)p_bias;
    float* stat = (float*)p_stat;

    const size_t SBb = (size_t)CCH * NTOK;
    bf16* qb  = qkvb;                           // [tok][ch]
    bf16* kb  = qkvb + BATCH * SBb;
    bf16* vtb = qkvb + 2 * BATCH * SBb;

    cudaFuncSetAttribute(bgemm_qkv, cudaFuncAttributeMaxDynamicSharedMemorySize, SMEM_DYN);
    cudaFuncSetAttribute(fattn, cudaFuncAttributeMaxDynamicSharedMemorySize, FSMEM);

    // 0) convert+pack weights / biases
    convw_kernel<<<256, 256>>>(wq, wk, wv, wo, bq, bk, bv,
                               wqb, wqb + CCH*CCH, wqb + 2*CCH*CCH, wob, biasqkv);

    // 1) GroupNorm (stats + apply), bf16 out [c][tok]
    gn_stats_kernel<<<BATCH * GROUPS * 4, 256>>>(x, stat);
    gn_apply_kernel<<<BATCH * GROUPS * 4, 256>>>(x, stat, gn_w, gn_b, xnb);

    // 2) q,k,v transposed projections -> [tok][ch] bf16 (q pre-scaled 1/16)
    bgemm_qkv<<<dim3(CCH/128, 96, BATCH), 128, SMEM_DYN>>>(
        xnb, wqb, biasqkv, qkvb, NTOK, SBb);

    // 3) fused attention + output projection + residual -> out fp32
    fattn<<<dim3(NTOK/128, BATCH), 256, FSMEM>>>(qb, kb, vtb, wob, bo, x, out);
}

// round 14
// speedup vs baseline: 1.3686x; 1.0663x over previous
#include <cuda_runtime.h>
#include <cuda_bf16.h>
#include <cstdint>
#include <cstddef>

#define BATCH 4
#define CCH 256
#define NTOK 4096
#define GROUPS 32
#define CPG 8
#define EPSV 1e-6f

typedef __nv_bfloat16 bf16;

// ---------------- scratch ----------------
__device__ uint4 g_xnb4 [(size_t)BATCH * CCH * NTOK / 8];        // GN out bf16 [c][tok]
__device__ uint4 g_qkvb4[(size_t)3 * BATCH * CCH * NTOK / 8];    // q,k,v all [tok][ch] bf16
__device__ uint4 g_wb4[4][CCH * CCH / 8];
__device__ float g_biasqkv[3 * CCH];
__device__ float g_gnstat[BATCH * GROUPS * 4 * 2];

// ---------------- asm helpers ----------------
__device__ __forceinline__ uint32_t smem_u32(const void* p) {
    uint32_t a;
    asm("{ .reg .u64 t; cvta.to.shared.u64 t, %1; cvt.u32.u64 %0, t; }"
        : "=r"(a) : "l"(p));
    return a;
}
__device__ __forceinline__ void ldsm4(uint32_t* r, uint32_t a) {
    asm volatile("ldmatrix.sync.aligned.m8n8.x4.shared.b16 {%0,%1,%2,%3}, [%4];"
        : "=r"(r[0]), "=r"(r[1]), "=r"(r[2]), "=r"(r[3]) : "r"(a));
}
__device__ __forceinline__ void ldsm4t(uint32_t* r, uint32_t a) {
    asm volatile("ldmatrix.sync.aligned.m8n8.x4.trans.shared.b16 {%0,%1,%2,%3}, [%4];"
        : "=r"(r[0]), "=r"(r[1]), "=r"(r[2]), "=r"(r[3]) : "r"(a));
}
__device__ __forceinline__ void mma16(float* c, const uint32_t* a,
                                      uint32_t b0, uint32_t b1) {
    asm volatile(
        "mma.sync.aligned.m16n8k16.row.col.f32.bf16.bf16.f32 "
        "{%0,%1,%2,%3}, {%4,%5,%6,%7}, {%8,%9}, {%0,%1,%2,%3};"
        : "+f"(c[0]), "+f"(c[1]), "+f"(c[2]), "+f"(c[3])
        : "r"(a[0]), "r"(a[1]), "r"(a[2]), "r"(a[3]), "r"(b0), "r"(b1));
}
__device__ __forceinline__ void cp16(uint32_t d, const void* s) {
    asm volatile("cp.async.cg.shared.global [%0], [%1], 16;" :: "r"(d), "l"(s));
}
#define CPCOMMIT asm volatile("cp.async.commit_group;" ::: "memory")
#define CPWAIT(n) asm volatile("cp.async.wait_group %0;" :: "n"(n) : "memory")

__device__ __forceinline__ uint32_t packbf(float a, float b) {
    __nv_bfloat162 h = __floats2bfloat162_rn(a, b);
    return *(uint32_t*)&h;
}

// ---------------------------------------------------------------------------
__global__ void convw_kernel(const float* wq, const float* wk,
                             const float* wv, const float* wo,
                             const float* bq, const float* bk, const float* bv,
                             bf16* w0, bf16* w1, bf16* w2, bf16* w3,
                             float* biasqkv) {
    int i = blockIdx.x * 256 + threadIdx.x;
    w0[i] = __float2bfloat16(wq[i]);
    w1[i] = __float2bfloat16(wk[i]);
    w2[i] = __float2bfloat16(wv[i]);
    w3[i] = __float2bfloat16(wo[i]);
    if (i < CCH) {
        biasqkv[i]           = bq[i];
        biasqkv[CCH + i]     = bk[i];
        biasqkv[2 * CCH + i] = bv[i];
    }
}

// ---------------------------------------------------------------------------
__global__ void gn_stats_kernel(const float* __restrict__ x,
                                float* __restrict__ stat) {
    const float4* xp = (const float4*)(x + (size_t)blockIdx.x * 8192);
    int tid = threadIdx.x;
    float s = 0.f, s2 = 0.f;
    #pragma unroll
    for (int i = 0; i < 8; i++) {
        float4 v = xp[tid + i * 256];
        s  += v.x + v.y + v.z + v.w;
        s2 += v.x*v.x + v.y*v.y + v.z*v.z + v.w*v.w;
    }
    __shared__ float sh0[256], sh1[256];
    sh0[tid] = s; sh1[tid] = s2;
    __syncthreads();
    for (int off = 128; off > 0; off >>= 1) {
        if (tid < off) { sh0[tid] += sh0[tid + off]; sh1[tid] += sh1[tid + off]; }
        __syncthreads();
    }
    if (tid == 0) {
        stat[blockIdx.x * 2]     = sh0[0];
        stat[blockIdx.x * 2 + 1] = sh1[0];
    }
}

__global__ void gn_apply_kernel(const float* __restrict__ x,
                                const float* __restrict__ stat,
                                const float* __restrict__ w,
                                const float* __restrict__ b,
                                bf16* __restrict__ xnb) {
    int blk = blockIdx.x;
    int bg  = blk >> 2;
    int grp = bg % GROUPS;
    float s  = stat[bg * 8 + 0] + stat[bg * 8 + 2] +
               stat[bg * 8 + 4] + stat[bg * 8 + 6];
    float s2 = stat[bg * 8 + 1] + stat[bg * 8 + 3] +
               stat[bg * 8 + 5] + stat[bg * 8 + 7];
    const float nall = (float)(CPG * NTOK);
    float mean = s / nall;
    float var  = s2 / nall - mean * mean;
    float rstd = rsqrtf(var + EPSV);

    size_t base = (size_t)blk * 8192;
    const float4* xp = (const float4*)(x + base);
    bf16* op = xnb + base;
    int tid = threadIdx.x;
    #pragma unroll
    for (int i = 0; i < 8; i++) {
        int idx = tid + i * 256;
        int ch = grp * CPG + (int)(((blk & 3) * 8192 + idx * 4) / NTOK);
        float sc = rstd * w[ch];
        float sb = b[ch] - mean * sc;
        float4 v = xp[idx];
        __nv_bfloat162 h0 = __floats2bfloat162_rn(v.x * sc + sb, v.y * sc + sb);
        __nv_bfloat162 h1 = __floats2bfloat162_rn(v.z * sc + sb, v.w * sc + sb);
        uint2 u;
        u.x = *(uint32_t*)&h0; u.y = *(uint32_t*)&h1;
        *(uint2*)(op + idx * 4) = u;
    }
}

// ---------------------------------------------------------------------------
// bf16 GEMM for QKV transposed projections (unchanged from R13).
// ---------------------------------------------------------------------------
#define ABYTES 18432u
#define STAGEB 36864u
#define SMEM_DYN (3 * 36864)

__global__ void __launch_bounds__(128, 2)
bgemm_qkv(const bf16* __restrict__ A, const bf16* __restrict__ B,
          const float* __restrict__ bias, void* __restrict__ Cv,
          int lda, size_t sA) {
    extern __shared__ __align__(16) char smem[];
    const int bz = blockIdx.z;

    int mat = blockIdx.y >> 5;
    B    += (size_t)mat * (CCH * CCH);
    bias += mat * CCH;
    size_t cext = (size_t)mat * BATCH * (size_t)NTOK * CCH;
    float osc = (mat == 0) ? 0.0625f : 1.0f;
    const int M0 = (blockIdx.y & 31) * 128;
    A += (size_t)bz * sA;

    const int N0 = blockIdx.x * 128;
    const int tid  = threadIdx.x;
    const int lane = tid & 31;
    const int wid  = tid >> 5;
    const int wm = wid >> 1;
    const int wn = wid & 1;
    const int g  = lane >> 2;
    const int t  = lane & 3;
    const int l7  = lane & 7;
    const int b3 = (lane >> 3) & 1;
    const int b4 = (lane >> 4) & 1;

    const uint32_t smem_u = smem_u32(smem);

    float acc[4][8][4];
    #pragma unroll
    for (int i = 0; i < 4; i++)
        #pragma unroll
        for (int j = 0; j < 8; j++)
            #pragma unroll
            for (int q = 0; q < 4; q++) acc[i][j][q] = 0.f;

    const int KT = CCH >> 6;

    auto stage = [&](int kt, int buf) {
        uint32_t ab = smem_u + (uint32_t)buf * STAGEB;
        uint32_t bbs = ab + ABYTES;
        int k0 = kt << 6;
        #pragma unroll
        for (int i = 0; i < 8; i++) {
            int c = tid + i * 128;
            int k = c >> 4, mc = c & 15;
            cp16(ab + (uint32_t)(k * 136 + mc * 8) * 2,
                 A + (size_t)(k0 + k) * lda + M0 + mc * 8);
        }
        #pragma unroll
        for (int i = 0; i < 8; i++) {
            int c = tid + i * 128;
            int n = c >> 3, kc = c & 7;
            cp16(bbs + (uint32_t)(n * 72 + kc * 8) * 2,
                 B + (size_t)(N0 + n) * CCH + k0 + kc * 8);
        }
    };

    stage(0, 0);
    CPCOMMIT;
    stage(1, 1);
    CPCOMMIT;

    for (int kt = 0; kt < KT; kt++) {
        CPWAIT(1);
        __syncthreads();
        if (kt + 2 < KT) stage(kt + 2, (kt + 2) % 3);
        CPCOMMIT;

        uint32_t ab = smem_u + (uint32_t)(kt % 3) * STAGEB;
        uint32_t bbs = ab + ABYTES;

        #pragma unroll
        for (int ks = 0; ks < 4; ks++) {
            uint32_t af[4][4];
            #pragma unroll
            for (int i = 0; i < 4; i++)
                ldsm4t(af[i], ab + 2u * (uint32_t)(
                    (ks * 16 + b4 * 8 + l7) * 136 + wm * 64 + i * 16 + b3 * 8));
            uint32_t bfr[4][4];
            #pragma unroll
            for (int j2 = 0; j2 < 4; j2++) {
                int nb = wn * 64 + j2 * 16;
                ldsm4(bfr[j2], bbs + 2u * (uint32_t)(
                    (nb + b4 * 8 + l7) * 72 + ks * 16 + b3 * 8));
            }
            #pragma unroll
            for (int j2 = 0; j2 < 4; j2++) {
                #pragma unroll
                for (int i = 0; i < 4; i++) {
                    mma16(acc[i][2*j2],     af[i], bfr[j2][0], bfr[j2][1]);
                    mma16(acc[i][2*j2 + 1], af[i], bfr[j2][2], bfr[j2][3]);
                }
            }
        }
    }

    bf16* C = (bf16*)Cv + cext + (size_t)bz * NTOK * CCH;
    #pragma unroll
    for (int i = 0; i < 4; i++) {
        int m = M0 + wm * 64 + i * 16 + g;
        #pragma unroll
        for (int j = 0; j < 8; j++) {
            int n = N0 + wn * 64 + j * 8 + 2 * t;
            float2 bn = *(const float2*)(bias + n);
            *(__nv_bfloat162*)(C + (size_t)m * CCH + n) =
                __floats2bfloat162_rn((acc[i][j][0] + bn.x) * osc,
                                      (acc[i][j][1] + bn.y) * osc);
            *(__nv_bfloat162*)(C + (size_t)(m + 8) * CCH + n) =
                __floats2bfloat162_rn((acc[i][j][2] + bn.x) * osc,
                                      (acc[i][j][3] + bn.y) * osc);
        }
    }
}

// ---------------------------------------------------------------------------
// Fused attention + output projection + residual. 2D warp tiling + P smem.
// CTA = (batch, 128-token i-tile); 8 warps = grid 4x2 (wm rows32, wn half).
// j-tile = 64 tokens (64 iters), K and V double-buffered.
// Invariant: entering iter j, pending = {K[j], V[j]}.
// MMA1: S[32r x 32jt]/warp -> exp -> P smem [128][72]; MMA2: O[32r x 128ch]/warp.
// Epilogue: Wo staged into the 4 dead K/V buffers; out = Wo·O^T + bo + x.
// ---------------------------------------------------------------------------
#define QOFF  0u
#define K0OFF 67584u
#define K1OFF 101376u
#define V0OFF 135168u
#define V1OFF 168960u
#define POFF  202752u
#define SUMOFF 221184u
#define FSMEM  222208

__global__ void __launch_bounds__(256, 1)
fattn(const bf16* __restrict__ q, const bf16* __restrict__ k,
      const bf16* __restrict__ vt, const bf16* __restrict__ wo,
      const float* __restrict__ bo, const float* __restrict__ x,
      float* __restrict__ out) {
    extern __shared__ __align__(16) char smem[];
    const int bz = blockIdx.y;
    const int i0 = blockIdx.x * 128;
    q   += (size_t)bz * NTOK * CCH;
    k   += (size_t)bz * NTOK * CCH;
    vt  += (size_t)bz * NTOK * CCH;
    x   += (size_t)bz * CCH * NTOK;
    out += (size_t)bz * CCH * NTOK;

    const int tid = threadIdx.x;
    const int lane = tid & 31;
    const int wid  = tid >> 5;
    const int wm = wid >> 1;          // 0..3: rows wm*32..+31
    const int wn = wid & 1;           // 0..1: jtok/ch half
    const int g  = lane >> 2;
    const int t  = lane & 3;
    const int l7  = lane & 7;
    const int l15 = lane & 15;
    const int b3 = (lane >> 3) & 1;
    const int b4 = (lane >> 4) & 1;
    const uint32_t su = smem_u32(smem);

    float O[2][16][4];
    #pragma unroll
    for (int i = 0; i < 2; i++)
        #pragma unroll
        for (int b = 0; b < 16; b++)
            #pragma unroll
            for (int qq = 0; qq < 4; qq++) O[i][b][qq] = 0.f;
    float rs[2][2] = {{0.f, 0.f}, {0.f, 0.f}};

    // Q: [128 tok][256 ch] stride 264
    auto stageQ = [&]() {
        #pragma unroll
        for (int i = 0; i < 16; i++) {
            int cc = tid + i * 256;
            int r = cc >> 5, c8 = cc & 31;
            cp16(su + QOFF + (uint32_t)(r * 264 + c8 * 8) * 2,
                 q + (size_t)(i0 + r) * CCH + c8 * 8);
        }
    };
    // K/V tile: 64 tokens x 256 ch, stride 264
    auto stage64 = [&](uint32_t off, const bf16* src, int j) {
        #pragma unroll
        for (int i = 0; i < 8; i++) {
            int cc = tid + i * 256;
            int r = cc >> 5, c8 = cc & 31;
            cp16(su + off + (uint32_t)(r * 264 + c8 * 8) * 2,
                 src + (size_t)(j * 64 + r) * CCH + c8 * 8);
        }
    };
    // Wo: 256 rows x 256 ch into the 4 dead 64-row K/V buffers
    auto stageWo = [&]() {
        const uint32_t bases[4] = {K0OFF, K1OFF, V0OFF, V1OFF};
        #pragma unroll
        for (int i = 0; i < 32; i++) {
            int cc = tid + i * 256;
            int r = cc >> 5, c8 = cc & 31;
            cp16(su + bases[r >> 6] + (uint32_t)((r & 63) * 264 + c8 * 8) * 2,
                 wo + (size_t)r * CCH + c8 * 8);
        }
    };

    stageQ();                CPCOMMIT;
    stage64(K0OFF, k, 0);    CPCOMMIT;
    stage64(V0OFF, vt, 0);   CPCOMMIT;
    // pending: {Q, K0, V0}

    bf16* Ps = (bf16*)(smem + POFF);

    for (int j = 0; j < 64; j++) {
        const uint32_t kb = su + ((j & 1) ? K1OFF : K0OFF);
        const uint32_t vb = su + ((j & 1) ? V1OFF : V0OFF);

        CPWAIT(1);           // j=0: Q+K0 ; j>0: K[j]
        __syncthreads();

        // ---- MMA1: S[32 rows][32 jtok] per warp ----
        float S[2][4][4];
        #pragma unroll
        for (int i = 0; i < 2; i++)
            #pragma unroll
            for (int s = 0; s < 4; s++)
                #pragma unroll
                for (int qq = 0; qq < 4; qq++) S[i][s][qq] = 0.f;

        #pragma unroll
        for (int ks = 0; ks < 16; ks++) {
            uint32_t a[2][4];
            #pragma unroll
            for (int i = 0; i < 2; i++)
                ldsm4(a[i], su + QOFF + 2u * (uint32_t)(
                    (wm * 32 + i * 16 + l15) * 264 + ks * 16 + b4 * 8));
            #pragma unroll
            for (int j2 = 0; j2 < 2; j2++) {
                uint32_t bfr[4];
                ldsm4(bfr, kb + 2u * (uint32_t)(
                    (wn * 32 + j2 * 16 + b4 * 8 + l7) * 264 + ks * 16 + b3 * 8));
                #pragma unroll
                for (int i = 0; i < 2; i++) {
                    mma16(S[i][2*j2],     a[i], bfr[0], bfr[1]);
                    mma16(S[i][2*j2 + 1], a[i], bfr[2], bfr[3]);
                }
            }
        }

        // ---- exp -> P smem [128][72] + row-sum partials ----
        #pragma unroll
        for (int i = 0; i < 2; i++) {
            int ml = wm * 32 + i * 16 + g;
            #pragma unroll
            for (int s = 0; s < 4; s++) {
                int nl = wn * 32 + s * 8 + 2 * t;
                float e0 = __expf(S[i][s][0]);
                float e1 = __expf(S[i][s][1]);
                float e2 = __expf(S[i][s][2]);
                float e3 = __expf(S[i][s][3]);
                rs[i][0] += e0 + e1;
                rs[i][1] += e2 + e3;
                *(__nv_bfloat162*)(Ps + ml * 72 + nl)       = __floats2bfloat162_rn(e0, e1);
                *(__nv_bfloat162*)(Ps + (ml + 8) * 72 + nl) = __floats2bfloat162_rn(e2, e3);
            }
        }
        __syncthreads();     // P written; K[j] reads done

        if (j < 63) {
            stage64((j & 1) ? K0OFF : K1OFF, k, j + 1);
            CPCOMMIT;        // pending: {V[j], K[j+1]}
            CPWAIT(1);       // completes V[j]
        } else {
            CPWAIT(0);       // completes V[63]
        }
        __syncthreads();     // V[j] visible

        // ---- MMA2: O[32 rows][128 ch] += P · V ----
        #pragma unroll
        for (int ks2 = 0; ks2 < 4; ks2++) {
            uint32_t pa[2][4];
            #pragma unroll
            for (int i = 0; i < 2; i++)
                ldsm4(pa[i], su + POFF + 2u * (uint32_t)(
                    (wm * 32 + i * 16 + l15) * 72 + ks2 * 16 + b4 * 8));
            #pragma unroll
            for (int j2 = 0; j2 < 8; j2++) {
                uint32_t bfr[4];
                ldsm4t(bfr, vb + 2u * (uint32_t)(
                    (ks2 * 16 + b3 * 8 + l7) * 264 + wn * 128 + j2 * 16 + b4 * 8));
                #pragma unroll
                for (int i = 0; i < 2; i++) {
                    mma16(O[i][2*j2],     pa[i], bfr[0], bfr[1]);
                    mma16(O[i][2*j2 + 1], pa[i], bfr[2], bfr[3]);
                }
            }
        }

        if (j < 63) {
            stage64((j & 1) ? V0OFF : V1OFF, vt, j + 1);
            CPCOMMIT;        // pending: {K[j+1], V[j+1]}
        } else {
            stageWo();       // all K/V buffers dead
            CPCOMMIT;        // pending: {Wo}
        }
    }

    // ---- row sums -> inverse ----
    float* ps = (float*)(smem + SUMOFF);   // [2][128]
    #pragma unroll
    for (int i = 0; i < 2; i++) {
        float s0 = rs[i][0], s1 = rs[i][1];
        s0 += __shfl_xor_sync(0xffffffffu, s0, 1);
        s0 += __shfl_xor_sync(0xffffffffu, s0, 2);
        s1 += __shfl_xor_sync(0xffffffffu, s1, 1);
        s1 += __shfl_xor_sync(0xffffffffu, s1, 2);
        if (t == 0) {
            int r = wm * 32 + i * 16 + g;
            ps[wn * 128 + r]     = s0;
            ps[wn * 128 + r + 8] = s1;
        }
    }
    __syncthreads();
    if (tid < 128) ps[tid] = 1.f / (ps[tid] + ps[128 + tid]);
    __syncthreads();

    // ---- normalize O into Q region (Os [128][264]) ----
    bf16* Os = (bf16*)smem;
    #pragma unroll
    for (int i = 0; i < 2; i++) {
        int r0 = wm * 32 + i * 16 + g;
        int r1 = r0 + 8;
        float iv0 = ps[r0];
        float iv1 = ps[r1];
        #pragma unroll
        for (int b = 0; b < 16; b++) {
            int col = wn * 128 + b * 8 + 2 * t;
            *(__nv_bfloat162*)(Os + r0 * 264 + col) =
                __floats2bfloat162_rn(O[i][b][0] * iv0, O[i][b][1] * iv0);
            *(__nv_bfloat162*)(Os + r1 * 264 + col) =
                __floats2bfloat162_rn(O[i][b][2] * iv1, O[i][b][3] * iv1);
        }
    }
    CPWAIT(0);           // Wo staged
    __syncthreads();     // Os + Wo visible

    // ---- epilogue GEMM: out[256 co][128 tok] = Wo · Os^T + bo + x ----
    float acc[2][16][4];
    #pragma unroll
    for (int i = 0; i < 2; i++)
        #pragma unroll
        for (int b = 0; b < 16; b++)
            #pragma unroll
            for (int qq = 0; qq < 4; qq++) acc[i][b][qq] = 0.f;

    const uint32_t bases[4] = {K0OFF, K1OFF, V0OFF, V1OFF};
    const uint32_t wo_off = bases[wid >> 1] + (uint32_t)((wid & 1) * 32) * 528;

    #pragma unroll
    for (int ks = 0; ks < 16; ks++) {
        uint32_t a2[2][4];
        #pragma unroll
        for (int i = 0; i < 2; i++)
            ldsm4(a2[i], su + wo_off + 2u * (uint32_t)(
                (i * 16 + l15) * 264 + ks * 16 + b4 * 8));
        #pragma unroll
        for (int j2 = 0; j2 < 8; j2++) {
            uint32_t bfr[4];
            ldsm4(bfr, su + QOFF + 2u * (uint32_t)(
                (j2 * 16 + b4 * 8 + l7) * 264 + ks * 16 + b3 * 8));
            #pragma unroll
            for (int i = 0; i < 2; i++) {
                mma16(acc[i][2*j2],     a2[i], bfr[0], bfr[1]);
                mma16(acc[i][2*j2 + 1], a2[i], bfr[2], bfr[3]);
            }
        }
    }

    #pragma unroll
    for (int i = 0; i < 2; i++) {
        int m = wid * 32 + i * 16 + g;          // output channel
        float bm0 = bo[m];
        float bm1 = bo[m + 8];
        #pragma unroll
        for (int b = 0; b < 16; b++) {
            int n = i0 + b * 8 + 2 * t;         // token
            float2 x0 = *(const float2*)(x + (size_t)m * NTOK + n);
            float2 x1 = *(const float2*)(x + (size_t)(m + 8) * NTOK + n);
            float2 v0, v1;
            v0.x = acc[i][b][0] + bm0 + x0.x;
            v0.y = acc[i][b][1] + bm0 + x0.y;
            v1.x = acc[i][b][2] + bm1 + x1.x;
            v1.y = acc[i][b][3] + bm1 + x1.y;
            *(float2*)(out + (size_t)m * NTOK + n)       = v0;
            *(float2*)(out + (size_t)(m + 8) * NTOK + n) = v1;
        }
    }
}

// ---------------------------------------------------------------------------
extern "C" void kernel_launch(void* const* d_in, const int* in_sizes, int n_in,
                              void* d_out, int out_size) {
    const float* x    = (const float*)d_in[0];
    const float* gn_w = (const float*)d_in[1];
    const float* gn_b = (const float*)d_in[2];
    const float* wq   = (const float*)d_in[3];
    const float* bq   = (const float*)d_in[4];
    const float* wk   = (const float*)d_in[5];
    const float* bk   = (const float*)d_in[6];
    const float* wv   = (const float*)d_in[7];
    const float* bv   = (const float*)d_in[8];
    const float* wo   = (const float*)d_in[9];
    const float* bo   = (const float*)d_in[10];
    float* out = (float*)d_out;

    void *p_xn, *p_qkv, *p_w, *p_bias, *p_stat;
    cudaGetSymbolAddress(&p_xn,   g_xnb4);
    cudaGetSymbolAddress(&p_qkv,  g_qkvb4);
    cudaGetSymbolAddress(&p_w,    g_wb4);
    cudaGetSymbolAddress(&p_bias, g_biasqkv);
    cudaGetSymbolAddress(&p_stat, g_gnstat);

    bf16* xnb  = (bf16*)p_xn;
    bf16* qkvb = (bf16*)p_qkv;
    bf16* wqb  = (bf16*)p_w;
    bf16* wob  = wqb + 3 * CCH * CCH;
    float* biasqkv = (float*)p_bias;
    float* stat = (float*)p_stat;

    const size_t SBb = (size_t)CCH * NTOK;
    bf16* qb  = qkvb;                           // [tok][ch]
    bf16* kb  = qkvb + BATCH * SBb;
    bf16* vtb = qkvb + 2 * BATCH * SBb;

    cudaFuncSetAttribute(bgemm_qkv, cudaFuncAttributeMaxDynamicSharedMemorySize, SMEM_DYN);
    cudaFuncSetAttribute(fattn, cudaFuncAttributeMaxDynamicSharedMemorySize, FSMEM);

    // 0) convert+pack weights / biases
    convw_kernel<<<256, 256>>>(wq, wk, wv, wo, bq, bk, bv,
                               wqb, wqb + CCH*CCH, wqb + 2*CCH*CCH, wob, biasqkv);

    // 1) GroupNorm (stats + apply), bf16 out [c][tok]
    gn_stats_kernel<<<BATCH * GROUPS * 4, 256>>>(x, stat);
    gn_apply_kernel<<<BATCH * GROUPS * 4, 256>>>(x, stat, gn_w, gn_b, xnb);

    // 2) q,k,v transposed projections -> [tok][ch] bf16 (q pre-scaled 1/16)
    bgemm_qkv<<<dim3(CCH/128, 96, BATCH), 128, SMEM_DYN>>>(
        xnb, wqb, biasqkv, qkvb, NTOK, SBb);

    // 3) fused attention + output projection + residual -> out fp32
    fattn<<<dim3(NTOK/128, BATCH), 256, FSMEM>>>(qb, kb, vtb, wob, bo, x, out);
}